// round 3
// baseline (speedup 1.0000x reference)
#include <cuda_runtime.h>
#include <cstdint>

#define NN   100000
#define EE   1600000
#define INC  512
#define HIDC 256
#define OUTC 32
#define ALPHA 0.1f

// ---------------- scratch (device globals; no allocation allowed) ----------------
__device__ float g_h1[(size_t)NN * HIDC];   // relu(x@W1^T+b1)
__device__ float g_xr[(size_t)NN * HIDC];   // h1 + relu(h1@Wr^T+br)
__device__ float g_h0[(size_t)NN * OUTC];   // xr@W2^T+b2
__device__ float g_hA[(size_t)NN * OUTC];
__device__ float g_hB[(size_t)NN * OUTC];
__device__ int   g_deg[NN];
__device__ float g_dinv[NN];
__device__ int   g_ptr[NN + 1];
__device__ int   g_fill[NN];
__device__ int   g_rows[EE];
__device__ float g_norms[EE];

// ---------------- fp32 tiled GEMM:  C = epi(A[M,K] @ B[N,K]^T + bias) ----------------
// MODE 0: +bias; MODE 1: relu(+bias); MODE 2: relu(+bias) + resid
template<int BM, int BN, int BK, int TM, int TN, int MODE>
__global__ void __launch_bounds__((BM / TM) * (BN / TN))
gemm_nt(const float* __restrict__ A, const float* __restrict__ B,
        const float* __restrict__ bias, float* __restrict__ C,
        const float* __restrict__ resid, int M, int N, int K)
{
    constexpr int TX = BN / TN;
    constexpr int TY = BM / TM;
    constexpr int NT = TX * TY;
    static_assert(TN == 4, "epilogue assumes TN==4");

    __shared__ float As[BK][BM];
    __shared__ float Bs[BK][BN];

    const int tid = threadIdx.x;
    const int tx = tid % TX;
    const int ty = tid / TX;
    const int bm = blockIdx.x * BM;
    const int bn = blockIdx.y * BN;

    float acc[TM][TN];
#pragma unroll
    for (int i = 0; i < TM; i++)
#pragma unroll
        for (int j = 0; j < TN; j++) acc[i][j] = 0.0f;

    for (int k0 = 0; k0 < K; k0 += BK) {
        // load A tile (guard rows: M not a multiple of BM)
#pragma unroll
        for (int l = 0; l < (BM * BK / 4) / NT; l++) {
            int idx = tid + l * NT;
            int row = idx / (BK / 4);
            int kc  = idx % (BK / 4);
            float4 v = make_float4(0.f, 0.f, 0.f, 0.f);
            int gr = bm + row;
            if (gr < M) v = *reinterpret_cast<const float4*>(&A[(size_t)gr * K + k0 + kc * 4]);
            As[kc * 4 + 0][row] = v.x;
            As[kc * 4 + 1][row] = v.y;
            As[kc * 4 + 2][row] = v.z;
            As[kc * 4 + 3][row] = v.w;
        }
        // load B tile (N,K exact multiples)
#pragma unroll
        for (int l = 0; l < (BN * BK / 4) / NT; l++) {
            int idx = tid + l * NT;
            int row = idx / (BK / 4);
            int kc  = idx % (BK / 4);
            float4 v = *reinterpret_cast<const float4*>(&B[(size_t)(bn + row) * K + k0 + kc * 4]);
            Bs[kc * 4 + 0][row] = v.x;
            Bs[kc * 4 + 1][row] = v.y;
            Bs[kc * 4 + 2][row] = v.z;
            Bs[kc * 4 + 3][row] = v.w;
        }
        __syncthreads();

#pragma unroll
        for (int k = 0; k < BK; k++) {
            float a[TM], b[TN];
#pragma unroll
            for (int i = 0; i < TM; i += 4)
                *reinterpret_cast<float4*>(&a[i]) =
                    *reinterpret_cast<const float4*>(&As[k][ty * TM + i]);
            *reinterpret_cast<float4*>(&b[0]) =
                *reinterpret_cast<const float4*>(&Bs[k][tx * TN]);
#pragma unroll
            for (int i = 0; i < TM; i++)
#pragma unroll
                for (int j = 0; j < TN; j++)
                    acc[i][j] = fmaf(a[i], b[j], acc[i][j]);
        }
        __syncthreads();
    }

    // epilogue
    const int col0 = bn + tx * TN;
    float4 bi = *reinterpret_cast<const float4*>(&bias[col0]);
#pragma unroll
    for (int i = 0; i < TM; i++) {
        int gr = bm + ty * TM + i;
        if (gr >= M) continue;
        float4 r;
        r.x = acc[i][0] + bi.x;
        r.y = acc[i][1] + bi.y;
        r.z = acc[i][2] + bi.z;
        r.w = acc[i][3] + bi.w;
        if (MODE >= 1) {
            r.x = fmaxf(r.x, 0.f); r.y = fmaxf(r.y, 0.f);
            r.z = fmaxf(r.z, 0.f); r.w = fmaxf(r.w, 0.f);
        }
        if (MODE == 2) {
            float4 rs = *reinterpret_cast<const float4*>(&resid[(size_t)gr * N + col0]);
            r.x += rs.x; r.y += rs.y; r.z += rs.z; r.w += rs.w;
        }
        *reinterpret_cast<float4*>(&C[(size_t)gr * N + col0]) = r;
    }
}

// ---------------- graph preprocessing (edge_index is INT32: JAX default x64-disabled) ----
__global__ void init_kernel(int* __restrict__ deg, int* __restrict__ fill)
{
    int v = blockIdx.x * blockDim.x + threadIdx.x;
    if (v < NN) { deg[v] = 1; fill[v] = 0; }  // deg starts at 1 (self loop)
}

__global__ void count_kernel(const int* __restrict__ ei, int* __restrict__ deg)
{
    int e = blockIdx.x * blockDim.x + threadIdx.x;
    if (e < EE) {
        int c = ei[EE + e];   // col = edge_index[1]
        if (c >= 0 && c < NN) atomicAdd(&deg[c], 1);
    }
}

__global__ void dinv_kernel(const int* __restrict__ deg, float* __restrict__ dinv)
{
    int v = blockIdx.x * blockDim.x + threadIdx.x;
    if (v < NN) dinv[v] = rsqrtf((float)deg[v]);
}

// single-block exclusive scan of indegree (deg-1) -> ptr
__global__ void __launch_bounds__(1024) scan_kernel(const int* __restrict__ deg, int* __restrict__ ptr)
{
    __shared__ int warpsums[32];
    __shared__ int s_carry;
    const int tid = threadIdx.x;
    const int lane = tid & 31;
    const int wid = tid >> 5;
    if (tid == 0) s_carry = 0;
    __syncthreads();

    for (int start = 0; start < NN; start += 1024) {
        int idx = start + tid;
        int v = (idx < NN) ? (deg[idx] - 1) : 0;
        int incl = v;
#pragma unroll
        for (int o = 1; o < 32; o <<= 1) {
            int t = __shfl_up_sync(0xFFFFFFFFu, incl, o);
            if (lane >= o) incl += t;
        }
        if (lane == 31) warpsums[wid] = incl;
        __syncthreads();
        if (wid == 0) {
            int w = warpsums[lane];
            int wi = w;
#pragma unroll
            for (int o = 1; o < 32; o <<= 1) {
                int t = __shfl_up_sync(0xFFFFFFFFu, wi, o);
                if (lane >= o) wi += t;
            }
            warpsums[lane] = wi - w;  // exclusive warp offsets
        }
        __syncthreads();
        int excl = s_carry + warpsums[wid] + incl - v;
        if (idx < NN) ptr[idx] = excl;
        __syncthreads();
        if (tid == 1023) s_carry += warpsums[31] + incl;  // block total
        __syncthreads();
    }
    if (threadIdx.x == 0) ptr[NN] = s_carry;
}

__global__ void fill_kernel(const int* __restrict__ ei,
                            const int* __restrict__ ptr, int* __restrict__ fill,
                            const float* __restrict__ dinv,
                            int* __restrict__ rows, float* __restrict__ norms)
{
    int e = blockIdx.x * blockDim.x + threadIdx.x;
    if (e < EE) {
        int r = ei[e];
        int c = ei[EE + e];
        if (c < 0 || c >= NN) return;                // mirrors count_kernel's filter
        int pos = ptr[c] + atomicAdd(&fill[c], 1);   // pos < EE by construction
        bool rok = (r >= 0 && r < NN);
        int rr = rok ? r : 0;
        rows[pos]  = rr;
        norms[pos] = rok ? dinv[rr] * dinv[c] : 0.0f;
    }
}

// ---------------- APPNP propagation: one warp per node, lane = channel ----------------
__global__ void __launch_bounds__(256)
prop_kernel(const float* __restrict__ src, const float* __restrict__ h0,
            float* __restrict__ dst,
            const int* __restrict__ ptr, const int* __restrict__ rows,
            const float* __restrict__ norms, const float* __restrict__ dinv)
{
    int gw = (blockIdx.x * blockDim.x + threadIdx.x) >> 5;
    int lane = threadIdx.x & 31;
    if (gw >= NN) return;

    int beg = ptr[gw];
    int end = ptr[gw + 1];

    float acc = 0.0f;
    int i = beg;
    for (; i + 4 <= end; i += 4) {
        int   r0 = rows[i + 0], r1 = rows[i + 1], r2 = rows[i + 2], r3 = rows[i + 3];
        float w0 = norms[i + 0], w1 = norms[i + 1], w2 = norms[i + 2], w3 = norms[i + 3];
        float v0 = src[(size_t)r0 * OUTC + lane];
        float v1 = src[(size_t)r1 * OUTC + lane];
        float v2 = src[(size_t)r2 * OUTC + lane];
        float v3 = src[(size_t)r3 * OUTC + lane];
        acc = fmaf(w0, v0, acc);
        acc = fmaf(w1, v1, acc);
        acc = fmaf(w2, v2, acc);
        acc = fmaf(w3, v3, acc);
    }
    for (; i < end; ++i)
        acc = fmaf(norms[i], src[(size_t)rows[i] * OUTC + lane], acc);

    // self loop: norm = dinv[v]^2
    float dv = dinv[gw];
    acc = fmaf(dv * dv, src[(size_t)gw * OUTC + lane], acc);

    dst[(size_t)gw * OUTC + lane] =
        fmaf(1.0f - ALPHA, acc, ALPHA * h0[(size_t)gw * OUTC + lane]);
}

// ---------------- launch ----------------
extern "C" void kernel_launch(void* const* d_in, const int* in_sizes, int n_in,
                              void* d_out, int out_size)
{
    // Identify inputs by element count (robust to metadata ordering).
    const float* x = nullptr; const int* ei = nullptr;
    const float *W1 = nullptr, *b1 = nullptr, *Wr = nullptr, *br = nullptr,
                *W2 = nullptr, *b2 = nullptr;
    for (int i = 0; i < n_in; i++) {
        switch (in_sizes[i]) {
            case 51200000: x  = (const float*)d_in[i]; break;              // N*IN_C
            case  3200000: ei = (const int*)d_in[i]; break;                // 2*E (int32)
            case   131072: W1 = (const float*)d_in[i]; break;              // 256*512
            case    65536: Wr = (const float*)d_in[i]; break;              // 256*256
            case     8192: W2 = (const float*)d_in[i]; break;              // 32*256
            case       32: b2 = (const float*)d_in[i]; break;
            case      256: if (!b1) b1 = (const float*)d_in[i];
                           else     br = (const float*)d_in[i]; break;
            default: break;
        }
    }
    // fallback to positional order if anything missing
    if (!x || !ei || !W1 || !b1 || !Wr || !br || !W2 || !b2) {
        x  = (const float*)d_in[0];     ei = (const int*)d_in[1];
        W1 = (const float*)d_in[2];     b1 = (const float*)d_in[3];
        Wr = (const float*)d_in[4];     br = (const float*)d_in[5];
        W2 = (const float*)d_in[6];     b2 = (const float*)d_in[7];
    }
    float* out = (float*)d_out;

    // Resolve scratch symbol addresses (host API, not a stream op: capture-safe).
    float *h1, *xr, *h0, *hA, *hB, *dinv, *norms;
    int *deg, *ptr, *fil, *rows;
    cudaGetSymbolAddress((void**)&h1,    g_h1);
    cudaGetSymbolAddress((void**)&xr,    g_xr);
    cudaGetSymbolAddress((void**)&h0,    g_h0);
    cudaGetSymbolAddress((void**)&hA,    g_hA);
    cudaGetSymbolAddress((void**)&hB,    g_hB);
    cudaGetSymbolAddress((void**)&dinv,  g_dinv);
    cudaGetSymbolAddress((void**)&norms, g_norms);
    cudaGetSymbolAddress((void**)&deg,   g_deg);
    cudaGetSymbolAddress((void**)&ptr,   g_ptr);
    cudaGetSymbolAddress((void**)&fil,   g_fill);
    cudaGetSymbolAddress((void**)&rows,  g_rows);

    // ---- MLP ----
    {
        dim3 g((NN + 127) / 128, HIDC / 64);
        gemm_nt<128, 64, 16, 8, 4, 1><<<g, 256>>>(x, W1, b1, h1, nullptr, NN, HIDC, INC);
    }
    {
        dim3 g((NN + 127) / 128, HIDC / 64);
        gemm_nt<128, 64, 16, 8, 4, 2><<<g, 256>>>(h1, Wr, br, xr, h1, NN, HIDC, HIDC);
    }
    {
        dim3 g((NN + 127) / 128, OUTC / 32);
        gemm_nt<128, 32, 32, 8, 4, 0><<<g, 128>>>(xr, W2, b2, h0, nullptr, NN, OUTC, HIDC);
    }

    // ---- CSR build ----
    init_kernel<<<(NN + 255) / 256, 256>>>(deg, fil);
    count_kernel<<<(EE + 255) / 256, 256>>>(ei, deg);
    dinv_kernel<<<(NN + 255) / 256, 256>>>(deg, dinv);
    scan_kernel<<<1, 1024>>>(deg, ptr);
    fill_kernel<<<(EE + 255) / 256, 256>>>(ei, ptr, fil, dinv, rows, norms);

    // ---- K = 10 propagation steps (ping-pong, last writes d_out) ----
    const int nblk = (NN * 32 + 255) / 256;  // one warp per node
    prop_kernel<<<nblk, 256>>>(h0, h0, hA, ptr, rows, norms, dinv);
    prop_kernel<<<nblk, 256>>>(hA, h0, hB, ptr, rows, norms, dinv);
    prop_kernel<<<nblk, 256>>>(hB, h0, hA, ptr, rows, norms, dinv);
    prop_kernel<<<nblk, 256>>>(hA, h0, hB, ptr, rows, norms, dinv);
    prop_kernel<<<nblk, 256>>>(hB, h0, hA, ptr, rows, norms, dinv);
    prop_kernel<<<nblk, 256>>>(hA, h0, hB, ptr, rows, norms, dinv);
    prop_kernel<<<nblk, 256>>>(hB, h0, hA, ptr, rows, norms, dinv);
    prop_kernel<<<nblk, 256>>>(hA, h0, hB, ptr, rows, norms, dinv);
    prop_kernel<<<nblk, 256>>>(hB, h0, hA, ptr, rows, norms, dinv);
    prop_kernel<<<nblk, 256>>>(hA, h0, out, ptr, rows, norms, dinv);
}

// round 5
// speedup vs baseline: 1.3571x; 1.3571x over previous
#include <cuda_runtime.h>
#include <cuda_bf16.h>
#include <cstdint>

#define NN   100000
#define EE   1600000
#define INC  512
#define HIDC 256
#define OUTC 32
#define ALPHA 0.1f

// ---------------- scratch (device globals; no allocation allowed) ----------------
__device__ float g_h1[(size_t)NN * HIDC];
__device__ float g_xr[(size_t)NN * HIDC];
__device__ float g_h0[(size_t)NN * OUTC];
__device__ float g_hA[(size_t)NN * OUTC];
__device__ float g_hB[(size_t)NN * OUTC];
__device__ int   g_deg[NN];
__device__ float g_dinv[NN];
__device__ int   g_ptr[NN + 1];
__device__ int   g_fill[NN];
__device__ int   g_rows[EE];
__device__ float g_norms[EE];

// ---------------- mma.sync bf16 helper (baseline PTX, no arch-"a" features) ----------------
__device__ __forceinline__ void mma16816(float* c, const uint32_t* a, const uint32_t* b)
{
    asm volatile(
        "mma.sync.aligned.m16n8k16.row.col.f32.bf16.bf16.f32 "
        "{%0,%1,%2,%3}, {%4,%5,%6,%7}, {%8,%9}, {%0,%1,%2,%3};"
        : "+f"(c[0]), "+f"(c[1]), "+f"(c[2]), "+f"(c[3])
        : "r"(a[0]), "r"(a[1]), "r"(a[2]), "r"(a[3]), "r"(b[0]), "r"(b[1]));
}

__device__ __forceinline__ uint32_t pack_bf16(__nv_bfloat16 a, __nv_bfloat16 b)
{
    unsigned short ua = *reinterpret_cast<unsigned short*>(&a);
    unsigned short ub = *reinterpret_cast<unsigned short*>(&b);
    return (uint32_t)ua | ((uint32_t)ub << 16);
}

// ---------------- tensor-core GEMM: C = epi(A[M,K] @ W[N,K]^T + bias) ----------------
// bf16 hi/lo split, fp32 acc: C += Ahi*Whi + Ahi*Wlo + Alo*Whi
// Block 128 x BN, 8 warps (4x2), warp tile 32 x (BN/2). MODE 0:+bias 1:relu 2:relu+resid
template<int BN, int MODE>
__global__ void __launch_bounds__(256)
gemm_mma(const float* __restrict__ A, const float* __restrict__ W,
         const float* __restrict__ bias, float* __restrict__ C,
         const float* __restrict__ resid, int M, int N, int K)
{
    constexpr int BM = 128, BK = 32, SA = BK + 4;   // padded smem row stride (elements)
    constexpr int NT = BN / 16;                     // 8-wide n-tiles per warp

    __shared__ __align__(16) __nv_bfloat16 sAh[BM * SA];
    __shared__ __align__(16) __nv_bfloat16 sAl[BM * SA];
    __shared__ __align__(16) __nv_bfloat16 sBh[BN * SA];
    __shared__ __align__(16) __nv_bfloat16 sBl[BN * SA];

    const int tid  = threadIdx.x;
    const int wid  = tid >> 5;
    const int lane = tid & 31;
    const int grp  = lane >> 2;      // 0..7
    const int qp   = lane & 3;       // 0..3
    const int wm   = wid >> 1;       // 0..3
    const int wn   = wid & 1;        // 0..1
    const int bm   = blockIdx.x * BM;
    const int bn   = blockIdx.y * BN;

    float acc[2][NT][4];
#pragma unroll
    for (int mt = 0; mt < 2; mt++)
#pragma unroll
        for (int nt = 0; nt < NT; nt++)
#pragma unroll
            for (int j = 0; j < 4; j++) acc[mt][nt][j] = 0.0f;

    for (int k0 = 0; k0 < K; k0 += BK) {
        // ---- fill A tile: fp32 -> (hi, lo) bf16 ----
#pragma unroll
        for (int l = 0; l < (BM * BK / 4) / 256; l++) {
            int idx = tid + l * 256;
            int row = idx >> 3;          // BK/4 = 8 float4 per row
            int c4  = idx & 7;
            float4 v = make_float4(0.f, 0.f, 0.f, 0.f);
            int gr = bm + row;
            if (gr < M)
                v = *reinterpret_cast<const float4*>(&A[(size_t)gr * K + k0 + c4 * 4]);
            __nv_bfloat16 h0 = __float2bfloat16(v.x), h1 = __float2bfloat16(v.y),
                          h2 = __float2bfloat16(v.z), h3 = __float2bfloat16(v.w);
            __nv_bfloat16 l0 = __float2bfloat16(v.x - __bfloat162float(h0));
            __nv_bfloat16 l1 = __float2bfloat16(v.y - __bfloat162float(h1));
            __nv_bfloat16 l2 = __float2bfloat16(v.z - __bfloat162float(h2));
            __nv_bfloat16 l3 = __float2bfloat16(v.w - __bfloat162float(h3));
            int e = row * SA + c4 * 4;   // even
            *reinterpret_cast<uint32_t*>(&sAh[e])     = pack_bf16(h0, h1);
            *reinterpret_cast<uint32_t*>(&sAh[e + 2]) = pack_bf16(h2, h3);
            *reinterpret_cast<uint32_t*>(&sAl[e])     = pack_bf16(l0, l1);
            *reinterpret_cast<uint32_t*>(&sAl[e + 2]) = pack_bf16(l2, l3);
        }
        // ---- fill B tile (weights, W[n][k] row-major) ----
        for (int idx = tid; idx < BN * (BK / 4); idx += 256) {
            int row = idx >> 3;
            int c4  = idx & 7;
            float4 v = *reinterpret_cast<const float4*>(&W[(size_t)(bn + row) * K + k0 + c4 * 4]);
            __nv_bfloat16 h0 = __float2bfloat16(v.x), h1 = __float2bfloat16(v.y),
                          h2 = __float2bfloat16(v.z), h3 = __float2bfloat16(v.w);
            __nv_bfloat16 l0 = __float2bfloat16(v.x - __bfloat162float(h0));
            __nv_bfloat16 l1 = __float2bfloat16(v.y - __bfloat162float(h1));
            __nv_bfloat16 l2 = __float2bfloat16(v.z - __bfloat162float(h2));
            __nv_bfloat16 l3 = __float2bfloat16(v.w - __bfloat162float(h3));
            int e = row * SA + c4 * 4;
            *reinterpret_cast<uint32_t*>(&sBh[e])     = pack_bf16(h0, h1);
            *reinterpret_cast<uint32_t*>(&sBh[e + 2]) = pack_bf16(h2, h3);
            *reinterpret_cast<uint32_t*>(&sBl[e])     = pack_bf16(l0, l1);
            *reinterpret_cast<uint32_t*>(&sBl[e + 2]) = pack_bf16(l2, l3);
        }
        __syncthreads();

        // ---- MMA over 2 k16 slices ----
#pragma unroll
        for (int kk = 0; kk < BK; kk += 16) {
            uint32_t ah[2][4], al[2][4];
#pragma unroll
            for (int mt = 0; mt < 2; mt++) {
                int r  = wm * 32 + mt * 16 + grp;
                int e0 = r * SA + kk + qp * 2;
                int e1 = (r + 8) * SA + kk + qp * 2;
                ah[mt][0] = *reinterpret_cast<const uint32_t*>(&sAh[e0]);
                ah[mt][1] = *reinterpret_cast<const uint32_t*>(&sAh[e1]);
                ah[mt][2] = *reinterpret_cast<const uint32_t*>(&sAh[e0 + 8]);
                ah[mt][3] = *reinterpret_cast<const uint32_t*>(&sAh[e1 + 8]);
                al[mt][0] = *reinterpret_cast<const uint32_t*>(&sAl[e0]);
                al[mt][1] = *reinterpret_cast<const uint32_t*>(&sAl[e1]);
                al[mt][2] = *reinterpret_cast<const uint32_t*>(&sAl[e0 + 8]);
                al[mt][3] = *reinterpret_cast<const uint32_t*>(&sAl[e1 + 8]);
            }
#pragma unroll
            for (int nt = 0; nt < NT; nt++) {
                int n = wn * (BN / 2) + nt * 8 + grp;
                int e = n * SA + kk + qp * 2;
                uint32_t bh[2], bl[2];
                bh[0] = *reinterpret_cast<const uint32_t*>(&sBh[e]);
                bh[1] = *reinterpret_cast<const uint32_t*>(&sBh[e + 8]);
                bl[0] = *reinterpret_cast<const uint32_t*>(&sBl[e]);
                bl[1] = *reinterpret_cast<const uint32_t*>(&sBl[e + 8]);
#pragma unroll
                for (int mt = 0; mt < 2; mt++) {
                    mma16816(acc[mt][nt], ah[mt], bh);
                    mma16816(acc[mt][nt], ah[mt], bl);
                    mma16816(acc[mt][nt], al[mt], bh);
                }
            }
        }
        __syncthreads();
    }

    // ---- epilogue: c frag (row = +grp/+8, col = 2*qp, 2*qp+1) ----
#pragma unroll
    for (int mt = 0; mt < 2; mt++) {
#pragma unroll
        for (int nt = 0; nt < NT; nt++) {
            int col  = bn + wn * (BN / 2) + nt * 8 + qp * 2;
            int row0 = bm + wm * 32 + mt * 16 + grp;
            int row1 = row0 + 8;
            float bx = bias[col], by = bias[col + 1];
            float o0 = acc[mt][nt][0] + bx, o1 = acc[mt][nt][1] + by;
            float o2 = acc[mt][nt][2] + bx, o3 = acc[mt][nt][3] + by;
            if (MODE >= 1) {
                o0 = fmaxf(o0, 0.f); o1 = fmaxf(o1, 0.f);
                o2 = fmaxf(o2, 0.f); o3 = fmaxf(o3, 0.f);
            }
            if (MODE == 2) {
                if (row0 < M) {
                    float2 r0 = *reinterpret_cast<const float2*>(&resid[(size_t)row0 * N + col]);
                    o0 += r0.x; o1 += r0.y;
                }
                if (row1 < M) {
                    float2 r1 = *reinterpret_cast<const float2*>(&resid[(size_t)row1 * N + col]);
                    o2 += r1.x; o3 += r1.y;
                }
            }
            if (row0 < M) {
                float2 s = make_float2(o0, o1);
                *reinterpret_cast<float2*>(&C[(size_t)row0 * N + col]) = s;
            }
            if (row1 < M) {
                float2 s = make_float2(o2, o3);
                *reinterpret_cast<float2*>(&C[(size_t)row1 * N + col]) = s;
            }
        }
    }
}

// ---------------- graph preprocessing (edge_index is int32) ----------------
__global__ void init_kernel(int* __restrict__ deg, int* __restrict__ fill)
{
    int v = blockIdx.x * blockDim.x + threadIdx.x;
    if (v < NN) { deg[v] = 1; fill[v] = 0; }
}

__global__ void count_kernel(const int* __restrict__ ei, int* __restrict__ deg)
{
    int e = blockIdx.x * blockDim.x + threadIdx.x;
    if (e < EE) {
        int c = ei[EE + e];
        if (c >= 0 && c < NN) atomicAdd(&deg[c], 1);
    }
}

__global__ void dinv_kernel(const int* __restrict__ deg, float* __restrict__ dinv)
{
    int v = blockIdx.x * blockDim.x + threadIdx.x;
    if (v < NN) dinv[v] = rsqrtf((float)deg[v]);
}

__global__ void __launch_bounds__(1024) scan_kernel(const int* __restrict__ deg, int* __restrict__ ptr)
{
    __shared__ int warpsums[32];
    __shared__ int s_carry;
    const int tid = threadIdx.x;
    const int lane = tid & 31;
    const int wid = tid >> 5;
    if (tid == 0) s_carry = 0;
    __syncthreads();

    for (int start = 0; start < NN; start += 1024) {
        int idx = start + tid;
        int v = (idx < NN) ? (deg[idx] - 1) : 0;
        int incl = v;
#pragma unroll
        for (int o = 1; o < 32; o <<= 1) {
            int t = __shfl_up_sync(0xFFFFFFFFu, incl, o);
            if (lane >= o) incl += t;
        }
        if (lane == 31) warpsums[wid] = incl;
        __syncthreads();
        if (wid == 0) {
            int w = warpsums[lane];
            int wi = w;
#pragma unroll
            for (int o = 1; o < 32; o <<= 1) {
                int t = __shfl_up_sync(0xFFFFFFFFu, wi, o);
                if (lane >= o) wi += t;
            }
            warpsums[lane] = wi - w;
        }
        __syncthreads();
        int excl = s_carry + warpsums[wid] + incl - v;
        if (idx < NN) ptr[idx] = excl;
        __syncthreads();
        if (tid == 1023) s_carry += warpsums[31] + incl;
        __syncthreads();
    }
    if (threadIdx.x == 0) ptr[NN] = s_carry;
}

__global__ void fill_kernel(const int* __restrict__ ei,
                            const int* __restrict__ ptr, int* __restrict__ fill,
                            const float* __restrict__ dinv,
                            int* __restrict__ rows, float* __restrict__ norms)
{
    int e = blockIdx.x * blockDim.x + threadIdx.x;
    if (e < EE) {
        int r = ei[e];
        int c = ei[EE + e];
        if (c < 0 || c >= NN) return;
        int pos = ptr[c] + atomicAdd(&fill[c], 1);
        bool rok = (r >= 0 && r < NN);
        int rr = rok ? r : 0;
        rows[pos]  = rr;
        norms[pos] = rok ? dinv[rr] * dinv[c] : 0.0f;
    }
}

// ---------------- APPNP propagation: one warp per node, lane = channel ----------------
__global__ void __launch_bounds__(256)
prop_kernel(const float* __restrict__ src, const float* __restrict__ h0,
            float* __restrict__ dst,
            const int* __restrict__ ptr, const int* __restrict__ rows,
            const float* __restrict__ norms, const float* __restrict__ dinv)
{
    int gw = (blockIdx.x * blockDim.x + threadIdx.x) >> 5;
    int lane = threadIdx.x & 31;
    if (gw >= NN) return;

    int beg = ptr[gw];
    int end = ptr[gw + 1];

    float acc = 0.0f;
    int i = beg;
    for (; i + 4 <= end; i += 4) {
        int   r0 = rows[i + 0], r1 = rows[i + 1], r2 = rows[i + 2], r3 = rows[i + 3];
        float w0 = norms[i + 0], w1 = norms[i + 1], w2 = norms[i + 2], w3 = norms[i + 3];
        float v0 = src[(size_t)r0 * OUTC + lane];
        float v1 = src[(size_t)r1 * OUTC + lane];
        float v2 = src[(size_t)r2 * OUTC + lane];
        float v3 = src[(size_t)r3 * OUTC + lane];
        acc = fmaf(w0, v0, acc);
        acc = fmaf(w1, v1, acc);
        acc = fmaf(w2, v2, acc);
        acc = fmaf(w3, v3, acc);
    }
    for (; i < end; ++i)
        acc = fmaf(norms[i], src[(size_t)rows[i] * OUTC + lane], acc);

    float dv = dinv[gw];
    acc = fmaf(dv * dv, src[(size_t)gw * OUTC + lane], acc);

    dst[(size_t)gw * OUTC + lane] =
        fmaf(1.0f - ALPHA, acc, ALPHA * h0[(size_t)gw * OUTC + lane]);
}

// ---------------- launch ----------------
extern "C" void kernel_launch(void* const* d_in, const int* in_sizes, int n_in,
                              void* d_out, int out_size)
{
    const float* x = nullptr; const int* ei = nullptr;
    const float *W1 = nullptr, *b1 = nullptr, *Wr = nullptr, *br = nullptr,
                *W2 = nullptr, *b2 = nullptr;
    for (int i = 0; i < n_in; i++) {
        switch (in_sizes[i]) {
            case 51200000: x  = (const float*)d_in[i]; break;
            case  3200000: ei = (const int*)d_in[i]; break;
            case   131072: W1 = (const float*)d_in[i]; break;
            case    65536: Wr = (const float*)d_in[i]; break;
            case     8192: W2 = (const float*)d_in[i]; break;
            case       32: b2 = (const float*)d_in[i]; break;
            case      256: if (!b1) b1 = (const float*)d_in[i];
                           else     br = (const float*)d_in[i]; break;
            default: break;
        }
    }
    if (!x || !ei || !W1 || !b1 || !Wr || !br || !W2 || !b2) {
        x  = (const float*)d_in[0];     ei = (const int*)d_in[1];
        W1 = (const float*)d_in[2];     b1 = (const float*)d_in[3];
        Wr = (const float*)d_in[4];     br = (const float*)d_in[5];
        W2 = (const float*)d_in[6];     b2 = (const float*)d_in[7];
    }
    float* out = (float*)d_out;

    float *h1, *xr, *h0, *hA, *hB, *dinv, *norms;
    int *deg, *ptr, *fil, *rows;
    cudaGetSymbolAddress((void**)&h1,    g_h1);
    cudaGetSymbolAddress((void**)&xr,    g_xr);
    cudaGetSymbolAddress((void**)&h0,    g_h0);
    cudaGetSymbolAddress((void**)&hA,    g_hA);
    cudaGetSymbolAddress((void**)&hB,    g_hB);
    cudaGetSymbolAddress((void**)&dinv,  g_dinv);
    cudaGetSymbolAddress((void**)&norms, g_norms);
    cudaGetSymbolAddress((void**)&deg,   g_deg);
    cudaGetSymbolAddress((void**)&ptr,   g_ptr);
    cudaGetSymbolAddress((void**)&fil,   g_fill);
    cudaGetSymbolAddress((void**)&rows,  g_rows);

    // ---- MLP (tensor cores via mma.sync, bf16 split) ----
    const int ntiles = (NN + 127) / 128;
    gemm_mma<64, 1><<<dim3(ntiles, HIDC / 64), 256>>>(x,  W1, b1, h1, nullptr, NN, HIDC, INC);
    gemm_mma<64, 2><<<dim3(ntiles, HIDC / 64), 256>>>(h1, Wr, br, xr, h1,      NN, HIDC, HIDC);
    gemm_mma<32, 0><<<dim3(ntiles, OUTC / 32), 256>>>(xr, W2, b2, h0, nullptr, NN, OUTC, HIDC);

    // ---- CSR build ----
    init_kernel<<<(NN + 255) / 256, 256>>>(deg, fil);
    count_kernel<<<(EE + 255) / 256, 256>>>(ei, deg);
    dinv_kernel<<<(NN + 255) / 256, 256>>>(deg, dinv);
    scan_kernel<<<1, 1024>>>(deg, ptr);
    fill_kernel<<<(EE + 255) / 256, 256>>>(ei, ptr, fil, dinv, rows, norms);

    // ---- K = 10 propagation steps ----
    const int nblk = (NN * 32 + 255) / 256;
    prop_kernel<<<nblk, 256>>>(h0, h0, hA, ptr, rows, norms, dinv);
    prop_kernel<<<nblk, 256>>>(hA, h0, hB, ptr, rows, norms, dinv);
    prop_kernel<<<nblk, 256>>>(hB, h0, hA, ptr, rows, norms, dinv);
    prop_kernel<<<nblk, 256>>>(hA, h0, hB, ptr, rows, norms, dinv);
    prop_kernel<<<nblk, 256>>>(hB, h0, hA, ptr, rows, norms, dinv);
    prop_kernel<<<nblk, 256>>>(hA, h0, hB, ptr, rows, norms, dinv);
    prop_kernel<<<nblk, 256>>>(hB, h0, hA, ptr, rows, norms, dinv);
    prop_kernel<<<nblk, 256>>>(hA, h0, hB, ptr, rows, norms, dinv);
    prop_kernel<<<nblk, 256>>>(hB, h0, hA, ptr, rows, norms, dinv);
    prop_kernel<<<nblk, 256>>>(hA, h0, out, ptr, rows, norms, dinv);
}

// round 10
// speedup vs baseline: 1.5426x; 1.1366x over previous
#include <cuda_runtime.h>
#include <cuda_bf16.h>
#include <cstdint>

#define NN   100000
#define EE   1600000
#define INC  512
#define HIDC 256
#define OUTC 32
#define ALPHA 0.1f

// ---------------- scratch (device globals; no allocation allowed) ----------------
__device__ float g_h1[(size_t)NN * HIDC];                 // relu(x@W1^T+b1), fp32 (resid)
__device__ float g_h0[(size_t)NN * OUTC];
__device__ float g_hA[(size_t)NN * OUTC];
__device__ float g_hB[(size_t)NN * OUTC];
__device__ int   g_deg[NN];
__device__ float g_dinv[NN];
__device__ int   g_ptr[NN + 1];
__device__ int   g_fill[NN];
__device__ int   g_rows[EE];
__device__ float g_norms[EE];
// split (hi|lo along K) bf16 images
__device__ __nv_bfloat16 g_x2 [(size_t)NN * 2 * INC];
__device__ __nv_bfloat16 g_h12[(size_t)NN * 2 * HIDC];
__device__ __nv_bfloat16 g_xr2[(size_t)NN * 2 * HIDC];
__device__ __nv_bfloat16 g_w1s[HIDC * 2 * INC];
__device__ __nv_bfloat16 g_wrs[HIDC * 2 * HIDC];
__device__ __nv_bfloat16 g_w2s[OUTC * 2 * HIDC];

// ---------------- PTX helpers (all baseline, no arch-"a" features) ----------------
__device__ __forceinline__ uint32_t cvta_smem(const void* p) {
    uint32_t a;
    asm("{ .reg .u64 t; cvta.to.shared.u64 t, %1; cvt.u32.u64 %0, t; }" : "=r"(a) : "l"(p));
    return a;
}
#define CP_ASYNC16(dst, src, sz) \
    asm volatile("cp.async.cg.shared.global [%0], [%1], 16, %2;" :: "r"(dst), "l"(src), "r"(sz))
#define CP_COMMIT() asm volatile("cp.async.commit_group;")
#define CP_WAIT1()  asm volatile("cp.async.wait_group 1;")
#define LDSM4(R, addr) \
    asm volatile("ldmatrix.sync.aligned.m8n8.x4.shared.b16 {%0,%1,%2,%3}, [%4];" \
                 : "=r"((R)[0]), "=r"((R)[1]), "=r"((R)[2]), "=r"((R)[3]) : "r"(addr))

__device__ __forceinline__ void mma16816(float* c, const uint32_t* a, uint32_t b0, uint32_t b1)
{
    asm volatile(
        "mma.sync.aligned.m16n8k16.row.col.f32.bf16.bf16.f32 "
        "{%0,%1,%2,%3}, {%4,%5,%6,%7}, {%8,%9}, {%0,%1,%2,%3};"
        : "+f"(c[0]), "+f"(c[1]), "+f"(c[2]), "+f"(c[3])
        : "r"(a[0]), "r"(a[1]), "r"(a[2]), "r"(a[3]), "r"(b0), "r"(b1));
}
__device__ __forceinline__ uint32_t pack_bf16(float a, float b)
{
    __nv_bfloat16 ha = __float2bfloat16(a), hb = __float2bfloat16(b);
    unsigned short ua = *reinterpret_cast<unsigned short*>(&ha);
    unsigned short ub = *reinterpret_cast<unsigned short*>(&hb);
    return (uint32_t)ua | ((uint32_t)ub << 16);
}

// ---------------- split: X[M,K] fp32 -> X2[M,2K] bf16 ([hi | lo] along K) ----------------
__global__ void split_act(const float* __restrict__ X, __nv_bfloat16* __restrict__ X2,
                          int M, int K)
{
    int idx = blockIdx.x * blockDim.x + threadIdx.x;
    int tot = M * (K / 4);
    if (idx >= tot) return;
    int r = idx / (K / 4);
    int c = (idx % (K / 4)) * 4;
    float4 v = *reinterpret_cast<const float4*>(&X[(size_t)r * K + c]);
    __nv_bfloat16 h0 = __float2bfloat16(v.x), h1 = __float2bfloat16(v.y),
                  h2 = __float2bfloat16(v.z), h3 = __float2bfloat16(v.w);
    float l0 = v.x - __bfloat162float(h0), l1 = v.y - __bfloat162float(h1);
    float l2 = v.z - __bfloat162float(h2), l3 = v.w - __bfloat162float(h3);
    size_t base = (size_t)r * 2 * K;
    unsigned short uh0 = *reinterpret_cast<unsigned short*>(&h0);
    unsigned short uh1 = *reinterpret_cast<unsigned short*>(&h1);
    unsigned short uh2 = *reinterpret_cast<unsigned short*>(&h2);
    unsigned short uh3 = *reinterpret_cast<unsigned short*>(&h3);
    *reinterpret_cast<uint2*>(&X2[base + c]) =
        make_uint2((uint32_t)uh0 | ((uint32_t)uh1 << 16), (uint32_t)uh2 | ((uint32_t)uh3 << 16));
    *reinterpret_cast<uint2*>(&X2[base + K + c]) =
        make_uint2(pack_bf16(l0, l1), pack_bf16(l2, l3));
}

// ---------------- bf16 GEMM, 3-phase compensated split -------------------------------
// A2/W2 are [M,2K] bf16 ([hi | lo] along K). Stages run hi*hi, lo*hi, hi*lo:
//   phase 0: kA = t*BK,     kW = t*BK
//   phase 1: kA = K + t*BK, kW = t*BK
//   phase 2: kA = t*BK,     kW = K + t*BK
// MODE 1: relu, write Cf fp32 + C2 split    (layer 1)
// MODE 2: relu + resid, write C2 split only (layer 2)
// MODE 0: bias only, write Cf fp32          (layer 3)
template<int BN, int K, int MODE>
__global__ void __launch_bounds__(256)
gemm_bf16(const __nv_bfloat16* __restrict__ A2, const __nv_bfloat16* __restrict__ W2,
          const float* __restrict__ bias, float* __restrict__ Cf,
          __nv_bfloat16* __restrict__ C2, const float* __restrict__ resid, int M, int N)
{
    constexpr int BM = 128, BK = 64;
    constexpr int K2 = 2 * K;                // physical row length
    constexpr int TPK = K / BK;              // stages per phase
    constexpr int NS = 3 * TPK;              // total stages
    constexpr int SROW = 72;                 // padded smem row stride (bf16 elems) = 144B
    constexpr int ABYTES = BM * SROW * 2;    // 18432
    constexpr int BBYTES = BN * SROW * 2;
    constexpr int NGRP = BN / 32;            // n16 groups per warp (warp covers BN/2 cols)

    extern __shared__ __align__(16) char dsm[];
    const uint32_t s0 = cvta_smem(dsm);

    const int tid  = threadIdx.x;
    const int wid  = tid >> 5;
    const int lane = tid & 31;
    const int grp  = lane >> 2;
    const int qp   = lane & 3;
    const int wm   = wid >> 1;               // 0..3
    const int wn   = wid & 1;                // 0..1
    const int bm   = blockIdx.x * BM;
    const int bn   = blockIdx.y * BN;

    const int lrow = lane & 15;
    const int lkh  = lane >> 4;
    const uint32_t aoff = (uint32_t)(wm * 32 + lrow) * (SROW * 2) + lkh * 16;
    const uint32_t boff = (uint32_t)(wn * (BN / 2) + lrow) * (SROW * 2) + lkh * 16;

    float acc[2][BN / 16][4];
#pragma unroll
    for (int mt = 0; mt < 2; mt++)
#pragma unroll
        for (int nt = 0; nt < BN / 16; nt++)
#pragma unroll
            for (int j = 0; j < 4; j++) acc[mt][nt][j] = 0.0f;

    // cp.async tile fill for pipeline stage `stage` into buffer `buf`
    auto fill = [&](int buf, int stage) {
        int phase = stage / TPK;
        int t     = stage % TPK;
        int kA = ((phase == 1) ? K : 0) + t * BK;
        int kW = ((phase == 2) ? K : 0) + t * BK;
        uint32_t sa = s0 + buf * ABYTES;
        uint32_t sb = s0 + 2 * ABYTES + buf * BBYTES;
        // A: 128 rows x 8 chunks of 16B
#pragma unroll
        for (int i = 0; i < 4; i++) {
            int idx = tid + i * 256;
            int row = idx >> 3, c = idx & 7;
            const __nv_bfloat16* src = A2 + (size_t)(bm + row) * K2 + kA + c * 8;
            uint32_t sz = (bm + row < M) ? 16u : 0u;
            CP_ASYNC16(sa + row * (SROW * 2) + c * 16, src, sz);
        }
        // B: BN rows x 8 chunks
#pragma unroll
        for (int i = 0; i < (BN * 8) / 256; i++) {
            int idx = tid + i * 256;
            int row = idx >> 3, c = idx & 7;
            const __nv_bfloat16* src = W2 + (size_t)(bn + row) * K2 + kW + c * 8;
            CP_ASYNC16(sb + row * (SROW * 2) + c * 16, src, 16u);
        }
    };

    fill(0, 0);
    CP_COMMIT();

    for (int s = 0; s < NS; s++) {
        if (s + 1 < NS) fill((s + 1) & 1, s + 1);
        CP_COMMIT();
        CP_WAIT1();
        __syncthreads();

        uint32_t abase = s0 + (s & 1) * ABYTES + aoff;
        uint32_t bbase = s0 + 2 * ABYTES + (s & 1) * BBYTES + boff;
#pragma unroll
        for (int ks = 0; ks < BK / 16; ks++) {
            uint32_t a0[4], a1[4];
            LDSM4(a0, abase + ks * 32);
            LDSM4(a1, abase + 16 * (SROW * 2) + ks * 32);
#pragma unroll
            for (int t = 0; t < NGRP; t++) {
                uint32_t bb[4];
                LDSM4(bb, bbase + t * 16 * (SROW * 2) + ks * 32);
                mma16816(acc[0][2 * t],     a0, bb[0], bb[2]);
                mma16816(acc[0][2 * t + 1], a0, bb[1], bb[3]);
                mma16816(acc[1][2 * t],     a1, bb[0], bb[2]);
                mma16816(acc[1][2 * t + 1], a1, bb[1], bb[3]);
            }
        }
        __syncthreads();
    }

    // ---- epilogue ----
#pragma unroll
    for (int mt = 0; mt < 2; mt++) {
        int row0 = bm + wm * 32 + mt * 16 + grp;
        int row1 = row0 + 8;
#pragma unroll
        for (int t = 0; t < NGRP; t++) {
#pragma unroll
            for (int h = 0; h < 2; h++) {
                int nt = 2 * t + h;
                int col = bn + wn * (BN / 2) + t * 16 + h * 8 + qp * 2;
                float bx = bias[col], by = bias[col + 1];
                float o0 = acc[mt][nt][0] + bx, o1 = acc[mt][nt][1] + by;
                float o2 = acc[mt][nt][2] + bx, o3 = acc[mt][nt][3] + by;
                if (MODE >= 1) {
                    o0 = fmaxf(o0, 0.f); o1 = fmaxf(o1, 0.f);
                    o2 = fmaxf(o2, 0.f); o3 = fmaxf(o3, 0.f);
                }
                if (MODE == 2) {
                    if (row0 < M) {
                        float2 r0 = *reinterpret_cast<const float2*>(&resid[(size_t)row0 * N + col]);
                        o0 += r0.x; o1 += r0.y;
                    }
                    if (row1 < M) {
                        float2 r1 = *reinterpret_cast<const float2*>(&resid[(size_t)row1 * N + col]);
                        o2 += r1.x; o3 += r1.y;
                    }
                }
                if (MODE != 2) {  // write fp32
                    if (row0 < M)
                        *reinterpret_cast<float2*>(&Cf[(size_t)row0 * N + col]) = make_float2(o0, o1);
                    if (row1 < M)
                        *reinterpret_cast<float2*>(&Cf[(size_t)row1 * N + col]) = make_float2(o2, o3);
                }
                if (MODE == 1 || MODE == 2) {  // write split bf16 [hi | lo]
                    if (row0 < M) {
                        size_t b0 = (size_t)row0 * 2 * N;
                        __nv_bfloat16 hh0 = __float2bfloat16(o0), hh1 = __float2bfloat16(o1);
                        unsigned short u0 = *reinterpret_cast<unsigned short*>(&hh0);
                        unsigned short u1 = *reinterpret_cast<unsigned short*>(&hh1);
                        *reinterpret_cast<uint32_t*>(&C2[b0 + col]) = (uint32_t)u0 | ((uint32_t)u1 << 16);
                        *reinterpret_cast<uint32_t*>(&C2[b0 + N + col]) =
                            pack_bf16(o0 - __bfloat162float(hh0), o1 - __bfloat162float(hh1));
                    }
                    if (row1 < M) {
                        size_t b1 = (size_t)row1 * 2 * N;
                        __nv_bfloat16 hh2 = __float2bfloat16(o2), hh3 = __float2bfloat16(o3);
                        unsigned short u2 = *reinterpret_cast<unsigned short*>(&hh2);
                        unsigned short u3 = *reinterpret_cast<unsigned short*>(&hh3);
                        *reinterpret_cast<uint32_t*>(&C2[b1 + col]) = (uint32_t)u2 | ((uint32_t)u3 << 16);
                        *reinterpret_cast<uint32_t*>(&C2[b1 + N + col]) =
                            pack_bf16(o2 - __bfloat162float(hh2), o3 - __bfloat162float(hh3));
                    }
                }
            }
        }
    }
}

// ---------------- graph preprocessing (edge_index is int32) ----------------
__global__ void init_kernel(int* __restrict__ deg, int* __restrict__ fill)
{
    int v = blockIdx.x * blockDim.x + threadIdx.x;
    if (v < NN) { deg[v] = 1; fill[v] = 0; }
}

__global__ void count_kernel(const int* __restrict__ ei, int* __restrict__ deg)
{
    int e = blockIdx.x * blockDim.x + threadIdx.x;
    if (e < EE) {
        int c = ei[EE + e];
        if (c >= 0 && c < NN) atomicAdd(&deg[c], 1);
    }
}

__global__ void dinv_kernel(const int* __restrict__ deg, float* __restrict__ dinv)
{
    int v = blockIdx.x * blockDim.x + threadIdx.x;
    if (v < NN) dinv[v] = rsqrtf((float)deg[v]);
}

__global__ void __launch_bounds__(1024) scan_kernel(const int* __restrict__ deg, int* __restrict__ ptr)
{
    __shared__ int warpsums[32];
    __shared__ int s_carry;
    const int tid = threadIdx.x;
    const int lane = tid & 31;
    const int wid = tid >> 5;
    if (tid == 0) s_carry = 0;
    __syncthreads();

    for (int start = 0; start < NN; start += 1024) {
        int idx = start + tid;
        int v = (idx < NN) ? (deg[idx] - 1) : 0;
        int incl = v;
#pragma unroll
        for (int o = 1; o < 32; o <<= 1) {
            int t = __shfl_up_sync(0xFFFFFFFFu, incl, o);
            if (lane >= o) incl += t;
        }
        if (lane == 31) warpsums[wid] = incl;
        __syncthreads();
        if (wid == 0) {
            int w = warpsums[lane];
            int wi = w;
#pragma unroll
            for (int o = 1; o < 32; o <<= 1) {
                int t = __shfl_up_sync(0xFFFFFFFFu, wi, o);
                if (lane >= o) wi += t;
            }
            warpsums[lane] = wi - w;
        }
        __syncthreads();
        int excl = s_carry + warpsums[wid] + incl - v;
        if (idx < NN) ptr[idx] = excl;
        __syncthreads();
        if (tid == 1023) s_carry += warpsums[31] + incl;
        __syncthreads();
    }
    if (threadIdx.x == 0) ptr[NN] = s_carry;
}

__global__ void fill_kernel(const int* __restrict__ ei,
                            const int* __restrict__ ptr, int* __restrict__ fill,
                            const float* __restrict__ dinv,
                            int* __restrict__ rows, float* __restrict__ norms)
{
    int e = blockIdx.x * blockDim.x + threadIdx.x;
    if (e < EE) {
        int r = ei[e];
        int c = ei[EE + e];
        if (c < 0 || c >= NN) return;
        int pos = ptr[c] + atomicAdd(&fill[c], 1);
        bool rok = (r >= 0 && r < NN);
        int rr = rok ? r : 0;
        rows[pos]  = rr;
        norms[pos] = rok ? dinv[rr] * dinv[c] : 0.0f;
    }
}

// ---------------- APPNP propagation: one warp per node, lane = channel ----------------
__global__ void __launch_bounds__(256)
prop_kernel(const float* __restrict__ src, const float* __restrict__ h0,
            float* __restrict__ dst,
            const int* __restrict__ ptr, const int* __restrict__ rows,
            const float* __restrict__ norms, const float* __restrict__ dinv)
{
    int gw = (blockIdx.x * blockDim.x + threadIdx.x) >> 5;
    int lane = threadIdx.x & 31;
    if (gw >= NN) return;

    int beg = ptr[gw];
    int end = ptr[gw + 1];

    float acc = 0.0f;
    int i = beg;
    for (; i + 4 <= end; i += 4) {
        int   r0 = rows[i + 0], r1 = rows[i + 1], r2 = rows[i + 2], r3 = rows[i + 3];
        float w0 = norms[i + 0], w1 = norms[i + 1], w2 = norms[i + 2], w3 = norms[i + 3];
        float v0 = src[(size_t)r0 * OUTC + lane];
        float v1 = src[(size_t)r1 * OUTC + lane];
        float v2 = src[(size_t)r2 * OUTC + lane];
        float v3 = src[(size_t)r3 * OUTC + lane];
        acc = fmaf(w0, v0, acc);
        acc = fmaf(w1, v1, acc);
        acc = fmaf(w2, v2, acc);
        acc = fmaf(w3, v3, acc);
    }
    for (; i < end; ++i)
        acc = fmaf(norms[i], src[(size_t)rows[i] * OUTC + lane], acc);

    float dv = dinv[gw];
    acc = fmaf(dv * dv, src[(size_t)gw * OUTC + lane], acc);

    dst[(size_t)gw * OUTC + lane] =
        fmaf(1.0f - ALPHA, acc, ALPHA * h0[(size_t)gw * OUTC + lane]);
}

// ---------------- launch ----------------
extern "C" void kernel_launch(void* const* d_in, const int* in_sizes, int n_in,
                              void* d_out, int out_size)
{
    const float* x = nullptr; const int* ei = nullptr;
    const float *W1 = nullptr, *b1 = nullptr, *Wr = nullptr, *br = nullptr,
                *W2 = nullptr, *b2 = nullptr;
    for (int i = 0; i < n_in; i++) {
        switch (in_sizes[i]) {
            case 51200000: x  = (const float*)d_in[i]; break;
            case  3200000: ei = (const int*)d_in[i]; break;
            case   131072: W1 = (const float*)d_in[i]; break;
            case    65536: Wr = (const float*)d_in[i]; break;
            case     8192: W2 = (const float*)d_in[i]; break;
            case       32: b2 = (const float*)d_in[i]; break;
            case      256: if (!b1) b1 = (const float*)d_in[i];
                           else     br = (const float*)d_in[i]; break;
            default: break;
        }
    }
    if (!x || !ei || !W1 || !b1 || !Wr || !br || !W2 || !b2) {
        x  = (const float*)d_in[0];     ei = (const int*)d_in[1];
        W1 = (const float*)d_in[2];     b1 = (const float*)d_in[3];
        Wr = (const float*)d_in[4];     br = (const float*)d_in[5];
        W2 = (const float*)d_in[6];     b2 = (const float*)d_in[7];
    }
    float* out = (float*)d_out;

    float *h1, *h0, *hA, *hB, *dinv, *norms;
    int *deg, *ptr, *fil, *rows;
    __nv_bfloat16 *x2, *h12, *xr2, *w1s, *wrs, *w2s;
    cudaGetSymbolAddress((void**)&h1,    g_h1);
    cudaGetSymbolAddress((void**)&h0,    g_h0);
    cudaGetSymbolAddress((void**)&hA,    g_hA);
    cudaGetSymbolAddress((void**)&hB,    g_hB);
    cudaGetSymbolAddress((void**)&dinv,  g_dinv);
    cudaGetSymbolAddress((void**)&norms, g_norms);
    cudaGetSymbolAddress((void**)&deg,   g_deg);
    cudaGetSymbolAddress((void**)&ptr,   g_ptr);
    cudaGetSymbolAddress((void**)&fil,   g_fill);
    cudaGetSymbolAddress((void**)&rows,  g_rows);
    cudaGetSymbolAddress((void**)&x2,    g_x2);
    cudaGetSymbolAddress((void**)&h12,   g_h12);
    cudaGetSymbolAddress((void**)&xr2,   g_xr2);
    cudaGetSymbolAddress((void**)&w1s,   g_w1s);
    cudaGetSymbolAddress((void**)&wrs,   g_wrs);
    cudaGetSymbolAddress((void**)&w2s,   g_w2s);

    // dynamic smem: 2*A(18432) + 2*B
    const int smem_128 = 2 * 18432 + 2 * 128 * 144;  // 73728
    const int smem_32  = 2 * 18432 + 2 * 32 * 144;   // 46080
    cudaFuncSetAttribute(gemm_bf16<128, INC,  1>, cudaFuncAttributeMaxDynamicSharedMemorySize, smem_128);
    cudaFuncSetAttribute(gemm_bf16<128, HIDC, 2>, cudaFuncAttributeMaxDynamicSharedMemorySize, smem_128);
    cudaFuncSetAttribute(gemm_bf16<32,  HIDC, 0>, cudaFuncAttributeMaxDynamicSharedMemorySize, smem_32);

    // ---- splits (x + weights) ----
    split_act<<<(NN * (INC / 4) + 255) / 256, 256>>>(x, x2, NN, INC);
    split_act<<<(HIDC * (INC / 4) + 255) / 256, 256>>>(W1, w1s, HIDC, INC);
    split_act<<<(HIDC * (HIDC / 4) + 255) / 256, 256>>>(Wr, wrs, HIDC, HIDC);
    split_act<<<(OUTC * (HIDC / 4) + 255) / 256, 256>>>(W2, w2s, OUTC, HIDC);

    // ---- MLP (bf16 3-phase compensated tensor-core GEMMs) ----
    const int ntiles = (NN + 127) / 128;
    gemm_bf16<128, INC,  1><<<dim3(ntiles, HIDC / 128), 256, smem_128>>>(
        x2,  w1s, b1, h1,      h12, nullptr, NN, HIDC);
    gemm_bf16<128, HIDC, 2><<<dim3(ntiles, HIDC / 128), 256, smem_128>>>(
        h12, wrs, br, nullptr, xr2, h1,      NN, HIDC);
    gemm_bf16<32,  HIDC, 0><<<dim3(ntiles, OUTC / 32), 256, smem_32>>>(
        xr2, w2s, b2, h0,      nullptr, nullptr, NN, OUTC);

    // ---- CSR build ----
    init_kernel<<<(NN + 255) / 256, 256>>>(deg, fil);
    count_kernel<<<(EE + 255) / 256, 256>>>(ei, deg);
    dinv_kernel<<<(NN + 255) / 256, 256>>>(deg, dinv);
    scan_kernel<<<1, 1024>>>(deg, ptr);
    fill_kernel<<<(EE + 255) / 256, 256>>>(ei, ptr, fil, dinv, rows, norms);

    // ---- K = 10 propagation steps ----
    const int nblk = (NN * 32 + 255) / 256;
    prop_kernel<<<nblk, 256>>>(h0, h0, hA, ptr, rows, norms, dinv);
    prop_kernel<<<nblk, 256>>>(hA, h0, hB, ptr, rows, norms, dinv);
    prop_kernel<<<nblk, 256>>>(hB, h0, hA, ptr, rows, norms, dinv);
    prop_kernel<<<nblk, 256>>>(hA, h0, hB, ptr, rows, norms, dinv);
    prop_kernel<<<nblk, 256>>>(hB, h0, hA, ptr, rows, norms, dinv);
    prop_kernel<<<nblk, 256>>>(hA, h0, hB, ptr, rows, norms, dinv);
    prop_kernel<<<nblk, 256>>>(hB, h0, hA, ptr, rows, norms, dinv);
    prop_kernel<<<nblk, 256>>>(hA, h0, hB, ptr, rows, norms, dinv);
    prop_kernel<<<nblk, 256>>>(hB, h0, hA, ptr, rows, norms, dinv);
    prop_kernel<<<nblk, 256>>>(hA, h0, out, ptr, rows, norms, dinv);
}

// round 12
// speedup vs baseline: 1.5634x; 1.0135x over previous
#include <cuda_runtime.h>
#include <cuda_bf16.h>
#include <cstdint>

#define NN   100000
#define EE   1600000
#define INC  512
#define HIDC 256
#define OUTC 32
#define ALPHA 0.1f

// ---------------- scratch (device globals; no allocation allowed) ----------------
__device__ float g_h0[(size_t)NN * OUTC];
__device__ float g_hA[(size_t)NN * OUTC];
__device__ float g_hB[(size_t)NN * OUTC];
__device__ int   g_deg[NN];
__device__ float g_dinv[NN];
__device__ int   g_ptr[NN + 1];
__device__ int   g_fill[NN];
__device__ int   g_rows[EE];
__device__ float g_norms[EE];
// split (hi|lo along K) bf16 images
__device__ __nv_bfloat16 g_x2 [(size_t)NN * 2 * INC];
__device__ __nv_bfloat16 g_h12[(size_t)NN * 2 * HIDC];
__device__ __nv_bfloat16 g_xr2[(size_t)NN * 2 * HIDC];
__device__ __nv_bfloat16 g_w1s[HIDC * 2 * INC];
__device__ __nv_bfloat16 g_wrs[HIDC * 2 * HIDC];
__device__ __nv_bfloat16 g_w2s[OUTC * 2 * HIDC];

// ---------------- side stream for CSR overlap (created at static init) ----------------
static cudaStream_t g_sB = nullptr;
static cudaEvent_t  g_evFork = nullptr, g_evJoin = nullptr;
struct StreamInit {
    StreamInit() {
        cudaStreamCreateWithFlags(&g_sB, cudaStreamNonBlocking);
        cudaEventCreateWithFlags(&g_evFork, cudaEventDisableTiming);
        cudaEventCreateWithFlags(&g_evJoin, cudaEventDisableTiming);
    }
};
static StreamInit g_stream_init;

// ---------------- PTX helpers (all baseline, no arch-"a" features) ----------------
__device__ __forceinline__ uint32_t cvta_smem(const void* p) {
    uint32_t a;
    asm("{ .reg .u64 t; cvta.to.shared.u64 t, %1; cvt.u32.u64 %0, t; }" : "=r"(a) : "l"(p));
    return a;
}
#define CP_ASYNC16(dst, src, sz) \
    asm volatile("cp.async.cg.shared.global [%0], [%1], 16, %2;" :: "r"(dst), "l"(src), "r"(sz))
#define CP_COMMIT() asm volatile("cp.async.commit_group;")
#define CP_WAIT1()  asm volatile("cp.async.wait_group 1;")
#define LDSM4(R, addr) \
    asm volatile("ldmatrix.sync.aligned.m8n8.x4.shared.b16 {%0,%1,%2,%3}, [%4];" \
                 : "=r"((R)[0]), "=r"((R)[1]), "=r"((R)[2]), "=r"((R)[3]) : "r"(addr))

__device__ __forceinline__ void mma16816(float* c, const uint32_t* a, uint32_t b0, uint32_t b1)
{
    asm volatile(
        "mma.sync.aligned.m16n8k16.row.col.f32.bf16.bf16.f32 "
        "{%0,%1,%2,%3}, {%4,%5,%6,%7}, {%8,%9}, {%0,%1,%2,%3};"
        : "+f"(c[0]), "+f"(c[1]), "+f"(c[2]), "+f"(c[3])
        : "r"(a[0]), "r"(a[1]), "r"(a[2]), "r"(a[3]), "r"(b0), "r"(b1));
}
__device__ __forceinline__ uint32_t pack_bf16(float a, float b)
{
    __nv_bfloat16 ha = __float2bfloat16(a), hb = __float2bfloat16(b);
    unsigned short ua = *reinterpret_cast<unsigned short*>(&ha);
    unsigned short ub = *reinterpret_cast<unsigned short*>(&hb);
    return (uint32_t)ua | ((uint32_t)ub << 16);
}

// ---------------- split: X[M,K] fp32 -> X2[M,2K] bf16 ([hi | lo] along K) ----------------
__global__ void split_act(const float* __restrict__ X, __nv_bfloat16* __restrict__ X2,
                          int M, int K)
{
    int idx = blockIdx.x * blockDim.x + threadIdx.x;
    int tot = M * (K / 4);
    if (idx >= tot) return;
    int r = idx / (K / 4);
    int c = (idx % (K / 4)) * 4;
    float4 v = *reinterpret_cast<const float4*>(&X[(size_t)r * K + c]);
    __nv_bfloat16 h0 = __float2bfloat16(v.x), h1 = __float2bfloat16(v.y),
                  h2 = __float2bfloat16(v.z), h3 = __float2bfloat16(v.w);
    float l0 = v.x - __bfloat162float(h0), l1 = v.y - __bfloat162float(h1);
    float l2 = v.z - __bfloat162float(h2), l3 = v.w - __bfloat162float(h3);
    size_t base = (size_t)r * 2 * K;
    unsigned short uh0 = *reinterpret_cast<unsigned short*>(&h0);
    unsigned short uh1 = *reinterpret_cast<unsigned short*>(&h1);
    unsigned short uh2 = *reinterpret_cast<unsigned short*>(&h2);
    unsigned short uh3 = *reinterpret_cast<unsigned short*>(&h3);
    *reinterpret_cast<uint2*>(&X2[base + c]) =
        make_uint2((uint32_t)uh0 | ((uint32_t)uh1 << 16), (uint32_t)uh2 | ((uint32_t)uh3 << 16));
    *reinterpret_cast<uint2*>(&X2[base + K + c]) =
        make_uint2(pack_bf16(l0, l1), pack_bf16(l2, l3));
}

// ---------------- bf16 GEMM, 3-phase compensated split -------------------------------
// A2/W2 are [M,2K] bf16 ([hi | lo] along K). Stages run hi*hi, lo*hi, hi*lo:
//   phase 0: kA = t*BK,     kW = t*BK
//   phase 1: kA = K + t*BK, kW = t*BK
//   phase 2: kA = t*BK,     kW = K + t*BK
// MODE 1: relu, write C2 split                        (layer 1)
// MODE 2: relu + resid(hi+lo of resid2), write C2     (layer 2)
// MODE 0: bias only, write Cf fp32                    (layer 3)
template<int BN, int K, int MODE>
__global__ void __launch_bounds__(256)
gemm_bf16(const __nv_bfloat16* __restrict__ A2, const __nv_bfloat16* __restrict__ W2,
          const float* __restrict__ bias, float* __restrict__ Cf,
          __nv_bfloat16* __restrict__ C2, const __nv_bfloat16* __restrict__ resid2,
          int M, int N)
{
    constexpr int BM = 128, BK = 64;
    constexpr int K2 = 2 * K;                // physical row length
    constexpr int TPK = K / BK;              // stages per phase
    constexpr int NS = 3 * TPK;              // total stages
    constexpr int SROW = 72;                 // padded smem row stride (bf16 elems) = 144B
    constexpr int ABYTES = BM * SROW * 2;    // 18432
    constexpr int BBYTES = BN * SROW * 2;
    constexpr int NGRP = BN / 32;            // n16 groups per warp (warp covers BN/2 cols)

    extern __shared__ __align__(16) char dsm[];
    const uint32_t s0 = cvta_smem(dsm);

    const int tid  = threadIdx.x;
    const int wid  = tid >> 5;
    const int lane = tid & 31;
    const int grp  = lane >> 2;
    const int qp   = lane & 3;
    const int wm   = wid >> 1;               // 0..3
    const int wn   = wid & 1;                // 0..1
    const int bm   = blockIdx.x * BM;
    const int bn   = blockIdx.y * BN;

    const int lrow = lane & 15;
    const int lkh  = lane >> 4;
    const uint32_t aoff = (uint32_t)(wm * 32 + lrow) * (SROW * 2) + lkh * 16;
    const uint32_t boff = (uint32_t)(wn * (BN / 2) + lrow) * (SROW * 2) + lkh * 16;

    float acc[2][BN / 16][4];
#pragma unroll
    for (int mt = 0; mt < 2; mt++)
#pragma unroll
        for (int nt = 0; nt < BN / 16; nt++)
#pragma unroll
            for (int j = 0; j < 4; j++) acc[mt][nt][j] = 0.0f;

    // cp.async tile fill for pipeline stage `stage` into buffer `buf`
    auto fill = [&](int buf, int stage) {
        int phase = stage / TPK;
        int t     = stage % TPK;
        int kA = ((phase == 1) ? K : 0) + t * BK;
        int kW = ((phase == 2) ? K : 0) + t * BK;
        uint32_t sa = s0 + buf * ABYTES;
        uint32_t sb = s0 + 2 * ABYTES + buf * BBYTES;
        // A: 128 rows x 8 chunks of 16B
#pragma unroll
        for (int i = 0; i < 4; i++) {
            int idx = tid + i * 256;
            int row = idx >> 3, c = idx & 7;
            const __nv_bfloat16* src = A2 + (size_t)(bm + row) * K2 + kA + c * 8;
            uint32_t sz = (bm + row < M) ? 16u : 0u;
            CP_ASYNC16(sa + row * (SROW * 2) + c * 16, src, sz);
        }
        // B: BN rows x 8 chunks
#pragma unroll
        for (int i = 0; i < (BN * 8) / 256; i++) {
            int idx = tid + i * 256;
            int row = idx >> 3, c = idx & 7;
            const __nv_bfloat16* src = W2 + (size_t)(bn + row) * K2 + kW + c * 8;
            CP_ASYNC16(sb + row * (SROW * 2) + c * 16, src, 16u);
        }
    };

    fill(0, 0);
    CP_COMMIT();

    for (int s = 0; s < NS; s++) {
        if (s + 1 < NS) fill((s + 1) & 1, s + 1);
        CP_COMMIT();
        CP_WAIT1();
        __syncthreads();

        uint32_t abase = s0 + (s & 1) * ABYTES + aoff;
        uint32_t bbase = s0 + 2 * ABYTES + (s & 1) * BBYTES + boff;
#pragma unroll
        for (int ks = 0; ks < BK / 16; ks++) {
            uint32_t a0[4], a1[4];
            LDSM4(a0, abase + ks * 32);
            LDSM4(a1, abase + 16 * (SROW * 2) + ks * 32);
#pragma unroll
            for (int t = 0; t < NGRP; t++) {
                uint32_t bb[4];
                LDSM4(bb, bbase + t * 16 * (SROW * 2) + ks * 32);
                mma16816(acc[0][2 * t],     a0, bb[0], bb[2]);
                mma16816(acc[0][2 * t + 1], a0, bb[1], bb[3]);
                mma16816(acc[1][2 * t],     a1, bb[0], bb[2]);
                mma16816(acc[1][2 * t + 1], a1, bb[1], bb[3]);
            }
        }
        __syncthreads();
    }

    // ---- epilogue ----
#pragma unroll
    for (int mt = 0; mt < 2; mt++) {
        int row0 = bm + wm * 32 + mt * 16 + grp;
        int row1 = row0 + 8;
#pragma unroll
        for (int t = 0; t < NGRP; t++) {
#pragma unroll
            for (int h = 0; h < 2; h++) {
                int nt = 2 * t + h;
                int col = bn + wn * (BN / 2) + t * 16 + h * 8 + qp * 2;
                float bx = bias[col], by = bias[col + 1];
                float o0 = acc[mt][nt][0] + bx, o1 = acc[mt][nt][1] + by;
                float o2 = acc[mt][nt][2] + bx, o3 = acc[mt][nt][3] + by;
                if (MODE >= 1) {
                    o0 = fmaxf(o0, 0.f); o1 = fmaxf(o1, 0.f);
                    o2 = fmaxf(o2, 0.f); o3 = fmaxf(o3, 0.f);
                }
                if (MODE == 2) {  // residual = hi + lo of split image
                    if (row0 < M) {
                        size_t b0 = (size_t)row0 * 2 * N;
                        __nv_bfloat162 vh = *reinterpret_cast<const __nv_bfloat162*>(&resid2[b0 + col]);
                        __nv_bfloat162 vl = *reinterpret_cast<const __nv_bfloat162*>(&resid2[b0 + N + col]);
                        o0 += __bfloat162float(vh.x) + __bfloat162float(vl.x);
                        o1 += __bfloat162float(vh.y) + __bfloat162float(vl.y);
                    }
                    if (row1 < M) {
                        size_t b1 = (size_t)row1 * 2 * N;
                        __nv_bfloat162 vh = *reinterpret_cast<const __nv_bfloat162*>(&resid2[b1 + col]);
                        __nv_bfloat162 vl = *reinterpret_cast<const __nv_bfloat162*>(&resid2[b1 + N + col]);
                        o2 += __bfloat162float(vh.x) + __bfloat162float(vl.x);
                        o3 += __bfloat162float(vh.y) + __bfloat162float(vl.y);
                    }
                }
                if (MODE == 0) {  // write fp32
                    if (row0 < M)
                        *reinterpret_cast<float2*>(&Cf[(size_t)row0 * N + col]) = make_float2(o0, o1);
                    if (row1 < M)
                        *reinterpret_cast<float2*>(&Cf[(size_t)row1 * N + col]) = make_float2(o2, o3);
                } else {          // write split bf16 [hi | lo]
                    if (row0 < M) {
                        size_t b0 = (size_t)row0 * 2 * N;
                        __nv_bfloat16 hh0 = __float2bfloat16(o0), hh1 = __float2bfloat16(o1);
                        unsigned short u0 = *reinterpret_cast<unsigned short*>(&hh0);
                        unsigned short u1 = *reinterpret_cast<unsigned short*>(&hh1);
                        *reinterpret_cast<uint32_t*>(&C2[b0 + col]) = (uint32_t)u0 | ((uint32_t)u1 << 16);
                        *reinterpret_cast<uint32_t*>(&C2[b0 + N + col]) =
                            pack_bf16(o0 - __bfloat162float(hh0), o1 - __bfloat162float(hh1));
                    }
                    if (row1 < M) {
                        size_t b1 = (size_t)row1 * 2 * N;
                        __nv_bfloat16 hh2 = __float2bfloat16(o2), hh3 = __float2bfloat16(o3);
                        unsigned short u2 = *reinterpret_cast<unsigned short*>(&hh2);
                        unsigned short u3 = *reinterpret_cast<unsigned short*>(&hh3);
                        *reinterpret_cast<uint32_t*>(&C2[b1 + col]) = (uint32_t)u2 | ((uint32_t)u3 << 16);
                        *reinterpret_cast<uint32_t*>(&C2[b1 + N + col]) =
                            pack_bf16(o2 - __bfloat162float(hh2), o3 - __bfloat162float(hh3));
                    }
                }
            }
        }
    }
}

// ---------------- graph preprocessing (edge_index is int32) ----------------
__global__ void init_kernel(int* __restrict__ deg, int* __restrict__ fill)
{
    int v = blockIdx.x * blockDim.x + threadIdx.x;
    if (v < NN) { deg[v] = 1; fill[v] = 0; }
}

__global__ void count_kernel(const int* __restrict__ ei, int* __restrict__ deg)
{
    int e = blockIdx.x * blockDim.x + threadIdx.x;
    if (e < EE) {
        int c = ei[EE + e];
        if (c >= 0 && c < NN) atomicAdd(&deg[c], 1);
    }
}

__global__ void dinv_kernel(const int* __restrict__ deg, float* __restrict__ dinv)
{
    int v = blockIdx.x * blockDim.x + threadIdx.x;
    if (v < NN) dinv[v] = rsqrtf((float)deg[v]);
}

__global__ void __launch_bounds__(1024) scan_kernel(const int* __restrict__ deg, int* __restrict__ ptr)
{
    __shared__ int warpsums[32];
    __shared__ int s_carry;
    const int tid = threadIdx.x;
    const int lane = tid & 31;
    const int wid = tid >> 5;
    if (tid == 0) s_carry = 0;
    __syncthreads();

    for (int start = 0; start < NN; start += 1024) {
        int idx = start + tid;
        int v = (idx < NN) ? (deg[idx] - 1) : 0;
        int incl = v;
#pragma unroll
        for (int o = 1; o < 32; o <<= 1) {
            int t = __shfl_up_sync(0xFFFFFFFFu, incl, o);
            if (lane >= o) incl += t;
        }
        if (lane == 31) warpsums[wid] = incl;
        __syncthreads();
        if (wid == 0) {
            int w = warpsums[lane];
            int wi = w;
#pragma unroll
            for (int o = 1; o < 32; o <<= 1) {
                int t = __shfl_up_sync(0xFFFFFFFFu, wi, o);
                if (lane >= o) wi += t;
            }
            warpsums[lane] = wi - w;
        }
        __syncthreads();
        int excl = s_carry + warpsums[wid] + incl - v;
        if (idx < NN) ptr[idx] = excl;
        __syncthreads();
        if (tid == 1023) s_carry += warpsums[31] + incl;
        __syncthreads();
    }
    if (threadIdx.x == 0) ptr[NN] = s_carry;
}

__global__ void fill_kernel(const int* __restrict__ ei,
                            const int* __restrict__ ptr, int* __restrict__ fill,
                            const float* __restrict__ dinv,
                            int* __restrict__ rows, float* __restrict__ norms)
{
    int e = blockIdx.x * blockDim.x + threadIdx.x;
    if (e < EE) {
        int r = ei[e];
        int c = ei[EE + e];
        if (c < 0 || c >= NN) return;
        int pos = ptr[c] + atomicAdd(&fill[c], 1);
        bool rok = (r >= 0 && r < NN);
        int rr = rok ? r : 0;
        rows[pos]  = rr;
        norms[pos] = rok ? dinv[rr] * dinv[c] : 0.0f;
    }
}

// ---------------- APPNP propagation: one warp per node, lane = channel ----------------
__global__ void __launch_bounds__(256)
prop_kernel(const float* __restrict__ src, const float* __restrict__ h0,
            float* __restrict__ dst,
            const int* __restrict__ ptr, const int* __restrict__ rows,
            const float* __restrict__ norms, const float* __restrict__ dinv)
{
    int gw = (blockIdx.x * blockDim.x + threadIdx.x) >> 5;
    int lane = threadIdx.x & 31;
    if (gw >= NN) return;

    int beg = ptr[gw];
    int end = ptr[gw + 1];

    float acc = 0.0f;
    int i = beg;
    for (; i + 4 <= end; i += 4) {
        int   r0 = rows[i + 0], r1 = rows[i + 1], r2 = rows[i + 2], r3 = rows[i + 3];
        float w0 = norms[i + 0], w1 = norms[i + 1], w2 = norms[i + 2], w3 = norms[i + 3];
        float v0 = src[(size_t)r0 * OUTC + lane];
        float v1 = src[(size_t)r1 * OUTC + lane];
        float v2 = src[(size_t)r2 * OUTC + lane];
        float v3 = src[(size_t)r3 * OUTC + lane];
        acc = fmaf(w0, v0, acc);
        acc = fmaf(w1, v1, acc);
        acc = fmaf(w2, v2, acc);
        acc = fmaf(w3, v3, acc);
    }
    for (; i < end; ++i)
        acc = fmaf(norms[i], src[(size_t)rows[i] * OUTC + lane], acc);

    float dv = dinv[gw];
    acc = fmaf(dv * dv, src[(size_t)gw * OUTC + lane], acc);

    dst[(size_t)gw * OUTC + lane] =
        fmaf(1.0f - ALPHA, acc, ALPHA * h0[(size_t)gw * OUTC + lane]);
}

// ---------------- launch ----------------
extern "C" void kernel_launch(void* const* d_in, const int* in_sizes, int n_in,
                              void* d_out, int out_size)
{
    const float* x = nullptr; const int* ei = nullptr;
    const float *W1 = nullptr, *b1 = nullptr, *Wr = nullptr, *br = nullptr,
                *W2 = nullptr, *b2 = nullptr;
    for (int i = 0; i < n_in; i++) {
        switch (in_sizes[i]) {
            case 51200000: x  = (const float*)d_in[i]; break;
            case  3200000: ei = (const int*)d_in[i]; break;
            case   131072: W1 = (const float*)d_in[i]; break;
            case    65536: Wr = (const float*)d_in[i]; break;
            case     8192: W2 = (const float*)d_in[i]; break;
            case       32: b2 = (const float*)d_in[i]; break;
            case      256: if (!b1) b1 = (const float*)d_in[i];
                           else     br = (const float*)d_in[i]; break;
            default: break;
        }
    }
    if (!x || !ei || !W1 || !b1 || !Wr || !br || !W2 || !b2) {
        x  = (const float*)d_in[0];     ei = (const int*)d_in[1];
        W1 = (const float*)d_in[2];     b1 = (const float*)d_in[3];
        Wr = (const float*)d_in[4];     br = (const float*)d_in[5];
        W2 = (const float*)d_in[6];     b2 = (const float*)d_in[7];
    }
    float* out = (float*)d_out;

    float *h0, *hA, *hB, *dinv, *norms;
    int *deg, *ptr, *fil, *rows;
    __nv_bfloat16 *x2, *h12, *xr2, *w1s, *wrs, *w2s;
    cudaGetSymbolAddress((void**)&h0,    g_h0);
    cudaGetSymbolAddress((void**)&hA,    g_hA);
    cudaGetSymbolAddress((void**)&hB,    g_hB);
    cudaGetSymbolAddress((void**)&dinv,  g_dinv);
    cudaGetSymbolAddress((void**)&norms, g_norms);
    cudaGetSymbolAddress((void**)&deg,   g_deg);
    cudaGetSymbolAddress((void**)&ptr,   g_ptr);
    cudaGetSymbolAddress((void**)&fil,   g_fill);
    cudaGetSymbolAddress((void**)&rows,  g_rows);
    cudaGetSymbolAddress((void**)&x2,    g_x2);
    cudaGetSymbolAddress((void**)&h12,   g_h12);
    cudaGetSymbolAddress((void**)&xr2,   g_xr2);
    cudaGetSymbolAddress((void**)&w1s,   g_w1s);
    cudaGetSymbolAddress((void**)&wrs,   g_wrs);
    cudaGetSymbolAddress((void**)&w2s,   g_w2s);

    // dynamic smem: 2*A(18432) + 2*B
    const int smem_256 = 2 * 18432 + 2 * 256 * 144;  // 110592
    const int smem_32  = 2 * 18432 + 2 * 32 * 144;   //  46080
    cudaFuncSetAttribute(gemm_bf16<256, INC,  1>, cudaFuncAttributeMaxDynamicSharedMemorySize, smem_256);
    cudaFuncSetAttribute(gemm_bf16<256, HIDC, 2>, cudaFuncAttributeMaxDynamicSharedMemorySize, smem_256);
    cudaFuncSetAttribute(gemm_bf16<32,  HIDC, 0>, cudaFuncAttributeMaxDynamicSharedMemorySize, smem_32);

    // ---- fork: CSR build runs on side stream, concurrent with splits+GEMMs ----
    cudaEventRecord(g_evFork, 0);
    cudaStreamWaitEvent(g_sB, g_evFork, 0);
    init_kernel <<<(NN + 255) / 256, 256, 0, g_sB>>>(deg, fil);
    count_kernel<<<(EE + 255) / 256, 256, 0, g_sB>>>(ei, deg);
    dinv_kernel <<<(NN + 255) / 256, 256, 0, g_sB>>>(deg, dinv);
    scan_kernel <<<1, 1024, 0, g_sB>>>(deg, ptr);
    fill_kernel <<<(EE + 255) / 256, 256, 0, g_sB>>>(ei, ptr, fil, dinv, rows, norms);
    cudaEventRecord(g_evJoin, g_sB);

    // ---- splits (x + weights) on main stream ----
    split_act<<<(NN * (INC / 4) + 255) / 256, 256>>>(x, x2, NN, INC);
    split_act<<<(HIDC * (INC / 4) + 255) / 256, 256>>>(W1, w1s, HIDC, INC);
    split_act<<<(HIDC * (HIDC / 4) + 255) / 256, 256>>>(Wr, wrs, HIDC, HIDC);
    split_act<<<(OUTC * (HIDC / 4) + 255) / 256, 256>>>(W2, w2s, OUTC, HIDC);

    // ---- MLP (bf16 3-phase compensated tensor-core GEMMs, full-N CTAs) ----
    const int ntiles = (NN + 127) / 128;
    gemm_bf16<256, INC,  1><<<ntiles, 256, smem_256>>>(
        x2,  w1s, b1, nullptr, h12, nullptr, NN, HIDC);
    gemm_bf16<256, HIDC, 2><<<ntiles, 256, smem_256>>>(
        h12, wrs, br, nullptr, xr2, h12,     NN, HIDC);
    gemm_bf16<32,  HIDC, 0><<<ntiles, 256, smem_32>>>(
        xr2, w2s, b2, h0,      nullptr, nullptr, NN, OUTC);

    // ---- join: CSR must be done before propagation ----
    cudaStreamWaitEvent(0, g_evJoin, 0);

    // ---- K = 10 propagation steps ----
    const int nblk = (NN * 32 + 255) / 256;
    prop_kernel<<<nblk, 256>>>(h0, h0, hA, ptr, rows, norms, dinv);
    prop_kernel<<<nblk, 256>>>(hA, h0, hB, ptr, rows, norms, dinv);
    prop_kernel<<<nblk, 256>>>(hB, h0, hA, ptr, rows, norms, dinv);
    prop_kernel<<<nblk, 256>>>(hA, h0, hB, ptr, rows, norms, dinv);
    prop_kernel<<<nblk, 256>>>(hB, h0, hA, ptr, rows, norms, dinv);
    prop_kernel<<<nblk, 256>>>(hA, h0, hB, ptr, rows, norms, dinv);
    prop_kernel<<<nblk, 256>>>(hB, h0, hA, ptr, rows, norms, dinv);
    prop_kernel<<<nblk, 256>>>(hA, h0, hB, ptr, rows, norms, dinv);
    prop_kernel<<<nblk, 256>>>(hB, h0, hA, ptr, rows, norms, dinv);
    prop_kernel<<<nblk, 256>>>(hA, h0, out, ptr, rows, norms, dinv);
}

// round 13
// speedup vs baseline: 1.6763x; 1.0722x over previous
#include <cuda_runtime.h>
#include <cuda_bf16.h>
#include <cstdint>

#define NN   100000
#define EE   1600000
#define INC  512
#define HIDC 256
#define OUTC 32
#define ALPHA 0.1f

// ---------------- scratch (device globals; no allocation allowed) ----------------
__device__ float g_h0[(size_t)NN * OUTC];
__device__ float g_hA[(size_t)NN * OUTC];
__device__ float g_hB[(size_t)NN * OUTC];
__device__ int   g_deg[NN];
__device__ float g_dinv[NN];
__device__ int   g_ptr[NN + 1];
__device__ int   g_fill[NN];
__device__ int   g_rows[EE];
__device__ float g_norms[EE];
// split (hi|lo along K) bf16 images
__device__ __nv_bfloat16 g_x2 [(size_t)NN * 2 * INC];
__device__ __nv_bfloat16 g_h12[(size_t)NN * 2 * HIDC];
__device__ __nv_bfloat16 g_xr2[(size_t)NN * 2 * HIDC];
__device__ __nv_bfloat16 g_w1s[HIDC * 2 * INC];
__device__ __nv_bfloat16 g_wrs[HIDC * 2 * HIDC];
__device__ __nv_bfloat16 g_w2s[OUTC * 2 * HIDC];

// ---------------- side stream for CSR overlap (created at static init) ----------------
static cudaStream_t g_sB = nullptr;
static cudaEvent_t  g_evFork = nullptr, g_evJoin = nullptr;
struct StreamInit {
    StreamInit() {
        cudaStreamCreateWithFlags(&g_sB, cudaStreamNonBlocking);
        cudaEventCreateWithFlags(&g_evFork, cudaEventDisableTiming);
        cudaEventCreateWithFlags(&g_evJoin, cudaEventDisableTiming);
    }
};
static StreamInit g_stream_init;

// ---------------- PTX helpers (all baseline, no arch-"a" features) ----------------
__device__ __forceinline__ uint32_t cvta_smem(const void* p) {
    uint32_t a;
    asm("{ .reg .u64 t; cvta.to.shared.u64 t, %1; cvt.u32.u64 %0, t; }" : "=r"(a) : "l"(p));
    return a;
}
#define CP_ASYNC16(dst, src, sz) \
    asm volatile("cp.async.cg.shared.global [%0], [%1], 16, %2;" :: "r"(dst), "l"(src), "r"(sz))
#define CP_COMMIT() asm volatile("cp.async.commit_group;")
#define CP_WAIT1()  asm volatile("cp.async.wait_group 1;")
#define LDSM4(R, addr) \
    asm volatile("ldmatrix.sync.aligned.m8n8.x4.shared.b16 {%0,%1,%2,%3}, [%4];" \
                 : "=r"((R)[0]), "=r"((R)[1]), "=r"((R)[2]), "=r"((R)[3]) : "r"(addr))

__device__ __forceinline__ void mma16816(float* c, const uint32_t* a, uint32_t b0, uint32_t b1)
{
    asm volatile(
        "mma.sync.aligned.m16n8k16.row.col.f32.bf16.bf16.f32 "
        "{%0,%1,%2,%3}, {%4,%5,%6,%7}, {%8,%9}, {%0,%1,%2,%3};"
        : "+f"(c[0]), "+f"(c[1]), "+f"(c[2]), "+f"(c[3])
        : "r"(a[0]), "r"(a[1]), "r"(a[2]), "r"(a[3]), "r"(b0), "r"(b1));
}
__device__ __forceinline__ uint32_t pack_bf16(float a, float b)
{
    __nv_bfloat16 ha = __float2bfloat16(a), hb = __float2bfloat16(b);
    unsigned short ua = *reinterpret_cast<unsigned short*>(&ha);
    unsigned short ub = *reinterpret_cast<unsigned short*>(&hb);
    return (uint32_t)ua | ((uint32_t)ub << 16);
}

// ---------------- split: X[M,K] fp32 -> X2[M,2K] bf16 ([hi | lo] along K) ----------------
__global__ void split_act(const float* __restrict__ X, __nv_bfloat16* __restrict__ X2,
                          int M, int K)
{
    int idx = blockIdx.x * blockDim.x + threadIdx.x;
    int tot = M * (K / 4);
    if (idx >= tot) return;
    int r = idx / (K / 4);
    int c = (idx % (K / 4)) * 4;
    float4 v = *reinterpret_cast<const float4*>(&X[(size_t)r * K + c]);
    __nv_bfloat16 h0 = __float2bfloat16(v.x), h1 = __float2bfloat16(v.y),
                  h2 = __float2bfloat16(v.z), h3 = __float2bfloat16(v.w);
    float l0 = v.x - __bfloat162float(h0), l1 = v.y - __bfloat162float(h1);
    float l2 = v.z - __bfloat162float(h2), l3 = v.w - __bfloat162float(h3);
    size_t base = (size_t)r * 2 * K;
    unsigned short uh0 = *reinterpret_cast<unsigned short*>(&h0);
    unsigned short uh1 = *reinterpret_cast<unsigned short*>(&h1);
    unsigned short uh2 = *reinterpret_cast<unsigned short*>(&h2);
    unsigned short uh3 = *reinterpret_cast<unsigned short*>(&h3);
    *reinterpret_cast<uint2*>(&X2[base + c]) =
        make_uint2((uint32_t)uh0 | ((uint32_t)uh1 << 16), (uint32_t)uh2 | ((uint32_t)uh3 << 16));
    *reinterpret_cast<uint2*>(&X2[base + K + c]) =
        make_uint2(pack_bf16(l0, l1), pack_bf16(l2, l3));
}

// ---------------- bf16 GEMM, 3-phase compensated split -------------------------------
// A2/W2 are [M,2K] bf16 ([hi | lo] along K). Stages run hi*hi, lo*hi, hi*lo:
//   phase 0: kA = t*BK,     kW = t*BK
//   phase 1: kA = K + t*BK, kW = t*BK
//   phase 2: kA = t*BK,     kW = K + t*BK
// MODE 1: relu, write C2 split                        (layer 1)
// MODE 2: relu + resid(hi+lo of resid2), write C2     (layer 2)
// MODE 0: bias only, write Cf fp32                    (layer 3)
template<int BN, int K, int MODE>
__global__ void __launch_bounds__(256)
gemm_bf16(const __nv_bfloat16* __restrict__ A2, const __nv_bfloat16* __restrict__ W2,
          const float* __restrict__ bias, float* __restrict__ Cf,
          __nv_bfloat16* __restrict__ C2, const __nv_bfloat16* __restrict__ resid2,
          int M, int N)
{
    constexpr int BM = 128, BK = 64;
    constexpr int K2 = 2 * K;                // physical row length
    constexpr int TPK = K / BK;              // stages per phase
    constexpr int NS = 3 * TPK;              // total stages
    constexpr int SROW = 72;                 // padded smem row stride (bf16 elems) = 144B
    constexpr int ABYTES = BM * SROW * 2;    // 18432
    constexpr int BBYTES = BN * SROW * 2;
    constexpr int NGRP = BN / 32;            // n16 groups per warp (warp covers BN/2 cols)

    extern __shared__ __align__(16) char dsm[];
    const uint32_t s0 = cvta_smem(dsm);

    const int tid  = threadIdx.x;
    const int wid  = tid >> 5;
    const int lane = tid & 31;
    const int grp  = lane >> 2;
    const int qp   = lane & 3;
    const int wm   = wid >> 1;               // 0..3
    const int wn   = wid & 1;                // 0..1
    const int bm   = blockIdx.x * BM;
    const int bn   = blockIdx.y * BN;

    const int lrow = lane & 15;
    const int lkh  = lane >> 4;
    const uint32_t aoff = (uint32_t)(wm * 32 + lrow) * (SROW * 2) + lkh * 16;
    const uint32_t boff = (uint32_t)(wn * (BN / 2) + lrow) * (SROW * 2) + lkh * 16;

    float acc[2][BN / 16][4];
#pragma unroll
    for (int mt = 0; mt < 2; mt++)
#pragma unroll
        for (int nt = 0; nt < BN / 16; nt++)
#pragma unroll
            for (int j = 0; j < 4; j++) acc[mt][nt][j] = 0.0f;

    // cp.async tile fill for pipeline stage `stage` into buffer `buf`
    auto fill = [&](int buf, int stage) {
        int phase = stage / TPK;
        int t     = stage % TPK;
        int kA = ((phase == 1) ? K : 0) + t * BK;
        int kW = ((phase == 2) ? K : 0) + t * BK;
        uint32_t sa = s0 + buf * ABYTES;
        uint32_t sb = s0 + 2 * ABYTES + buf * BBYTES;
        // A: 128 rows x 8 chunks of 16B
#pragma unroll
        for (int i = 0; i < 4; i++) {
            int idx = tid + i * 256;
            int row = idx >> 3, c = idx & 7;
            const __nv_bfloat16* src = A2 + (size_t)(bm + row) * K2 + kA + c * 8;
            uint32_t sz = (bm + row < M) ? 16u : 0u;
            CP_ASYNC16(sa + row * (SROW * 2) + c * 16, src, sz);
        }
        // B: BN rows x 8 chunks
#pragma unroll
        for (int i = 0; i < (BN * 8) / 256; i++) {
            int idx = tid + i * 256;
            int row = idx >> 3, c = idx & 7;
            const __nv_bfloat16* src = W2 + (size_t)(bn + row) * K2 + kW + c * 8;
            CP_ASYNC16(sb + row * (SROW * 2) + c * 16, src, 16u);
        }
    };

    fill(0, 0);
    CP_COMMIT();

    for (int s = 0; s < NS; s++) {
        if (s + 1 < NS) fill((s + 1) & 1, s + 1);
        CP_COMMIT();
        CP_WAIT1();
        __syncthreads();

        uint32_t abase = s0 + (s & 1) * ABYTES + aoff;
        uint32_t bbase = s0 + 2 * ABYTES + (s & 1) * BBYTES + boff;
#pragma unroll
        for (int ks = 0; ks < BK / 16; ks++) {
            uint32_t a0[4], a1[4];
            LDSM4(a0, abase + ks * 32);
            LDSM4(a1, abase + 16 * (SROW * 2) + ks * 32);
#pragma unroll
            for (int t = 0; t < NGRP; t++) {
                uint32_t bb[4];
                LDSM4(bb, bbase + t * 16 * (SROW * 2) + ks * 32);
                mma16816(acc[0][2 * t],     a0, bb[0], bb[2]);
                mma16816(acc[0][2 * t + 1], a0, bb[1], bb[3]);
                mma16816(acc[1][2 * t],     a1, bb[0], bb[2]);
                mma16816(acc[1][2 * t + 1], a1, bb[1], bb[3]);
            }
        }
        __syncthreads();
    }

    // ---- epilogue ----
#pragma unroll
    for (int mt = 0; mt < 2; mt++) {
        int row0 = bm + wm * 32 + mt * 16 + grp;
        int row1 = row0 + 8;
#pragma unroll
        for (int t = 0; t < NGRP; t++) {
#pragma unroll
            for (int h = 0; h < 2; h++) {
                int nt = 2 * t + h;
                int col = bn + wn * (BN / 2) + t * 16 + h * 8 + qp * 2;
                float bx = bias[col], by = bias[col + 1];
                float o0 = acc[mt][nt][0] + bx, o1 = acc[mt][nt][1] + by;
                float o2 = acc[mt][nt][2] + bx, o3 = acc[mt][nt][3] + by;
                if (MODE >= 1) {
                    o0 = fmaxf(o0, 0.f); o1 = fmaxf(o1, 0.f);
                    o2 = fmaxf(o2, 0.f); o3 = fmaxf(o3, 0.f);
                }
                if (MODE == 2) {  // residual = hi + lo of split image
                    if (row0 < M) {
                        size_t b0 = (size_t)row0 * 2 * N;
                        __nv_bfloat162 vh = *reinterpret_cast<const __nv_bfloat162*>(&resid2[b0 + col]);
                        __nv_bfloat162 vl = *reinterpret_cast<const __nv_bfloat162*>(&resid2[b0 + N + col]);
                        o0 += __bfloat162float(vh.x) + __bfloat162float(vl.x);
                        o1 += __bfloat162float(vh.y) + __bfloat162float(vl.y);
                    }
                    if (row1 < M) {
                        size_t b1 = (size_t)row1 * 2 * N;
                        __nv_bfloat162 vh = *reinterpret_cast<const __nv_bfloat162*>(&resid2[b1 + col]);
                        __nv_bfloat162 vl = *reinterpret_cast<const __nv_bfloat162*>(&resid2[b1 + N + col]);
                        o2 += __bfloat162float(vh.x) + __bfloat162float(vl.x);
                        o3 += __bfloat162float(vh.y) + __bfloat162float(vl.y);
                    }
                }
                if (MODE == 0) {  // write fp32
                    if (row0 < M)
                        *reinterpret_cast<float2*>(&Cf[(size_t)row0 * N + col]) = make_float2(o0, o1);
                    if (row1 < M)
                        *reinterpret_cast<float2*>(&Cf[(size_t)row1 * N + col]) = make_float2(o2, o3);
                } else {          // write split bf16 [hi | lo]
                    if (row0 < M) {
                        size_t b0 = (size_t)row0 * 2 * N;
                        __nv_bfloat16 hh0 = __float2bfloat16(o0), hh1 = __float2bfloat16(o1);
                        unsigned short u0 = *reinterpret_cast<unsigned short*>(&hh0);
                        unsigned short u1 = *reinterpret_cast<unsigned short*>(&hh1);
                        *reinterpret_cast<uint32_t*>(&C2[b0 + col]) = (uint32_t)u0 | ((uint32_t)u1 << 16);
                        *reinterpret_cast<uint32_t*>(&C2[b0 + N + col]) =
                            pack_bf16(o0 - __bfloat162float(hh0), o1 - __bfloat162float(hh1));
                    }
                    if (row1 < M) {
                        size_t b1 = (size_t)row1 * 2 * N;
                        __nv_bfloat16 hh2 = __float2bfloat16(o2), hh3 = __float2bfloat16(o3);
                        unsigned short u2 = *reinterpret_cast<unsigned short*>(&hh2);
                        unsigned short u3 = *reinterpret_cast<unsigned short*>(&hh3);
                        *reinterpret_cast<uint32_t*>(&C2[b1 + col]) = (uint32_t)u2 | ((uint32_t)u3 << 16);
                        *reinterpret_cast<uint32_t*>(&C2[b1 + N + col]) =
                            pack_bf16(o2 - __bfloat162float(hh2), o3 - __bfloat162float(hh3));
                    }
                }
            }
        }
    }
}

// ---------------- graph preprocessing (edge_index is int32) ----------------
__global__ void init_kernel(int* __restrict__ deg, int* __restrict__ fill)
{
    int v = blockIdx.x * blockDim.x + threadIdx.x;
    if (v < NN) { deg[v] = 1; fill[v] = 0; }
}

__global__ void count_kernel(const int* __restrict__ ei, int* __restrict__ deg)
{
    int e = blockIdx.x * blockDim.x + threadIdx.x;
    if (e < EE) {
        int c = ei[EE + e];
        if (c >= 0 && c < NN) atomicAdd(&deg[c], 1);
    }
}

__global__ void dinv_kernel(const int* __restrict__ deg, float* __restrict__ dinv)
{
    int v = blockIdx.x * blockDim.x + threadIdx.x;
    if (v < NN) dinv[v] = rsqrtf((float)deg[v]);
}

__global__ void __launch_bounds__(1024) scan_kernel(const int* __restrict__ deg, int* __restrict__ ptr)
{
    __shared__ int warpsums[32];
    __shared__ int s_carry;
    const int tid = threadIdx.x;
    const int lane = tid & 31;
    const int wid = tid >> 5;
    if (tid == 0) s_carry = 0;
    __syncthreads();

    for (int start = 0; start < NN; start += 1024) {
        int idx = start + tid;
        int v = (idx < NN) ? (deg[idx] - 1) : 0;
        int incl = v;
#pragma unroll
        for (int o = 1; o < 32; o <<= 1) {
            int t = __shfl_up_sync(0xFFFFFFFFu, incl, o);
            if (lane >= o) incl += t;
        }
        if (lane == 31) warpsums[wid] = incl;
        __syncthreads();
        if (wid == 0) {
            int w = warpsums[lane];
            int wi = w;
#pragma unroll
            for (int o = 1; o < 32; o <<= 1) {
                int t = __shfl_up_sync(0xFFFFFFFFu, wi, o);
                if (lane >= o) wi += t;
            }
            warpsums[lane] = wi - w;
        }
        __syncthreads();
        int excl = s_carry + warpsums[wid] + incl - v;
        if (idx < NN) ptr[idx] = excl;
        __syncthreads();
        if (tid == 1023) s_carry += warpsums[31] + incl;
        __syncthreads();
    }
    if (threadIdx.x == 0) ptr[NN] = s_carry;
}

__global__ void fill_kernel(const int* __restrict__ ei,
                            const int* __restrict__ ptr, int* __restrict__ fill,
                            const float* __restrict__ dinv,
                            int* __restrict__ rows, float* __restrict__ norms)
{
    int e = blockIdx.x * blockDim.x + threadIdx.x;
    if (e < EE) {
        int r = ei[e];
        int c = ei[EE + e];
        if (c < 0 || c >= NN) return;
        int pos = ptr[c] + atomicAdd(&fill[c], 1);
        bool rok = (r >= 0 && r < NN);
        int rr = rok ? r : 0;
        rows[pos]  = rr;
        norms[pos] = rok ? dinv[rr] * dinv[c] : 0.0f;
    }
}

// ---------------- APPNP propagation: one warp per node, lane = channel ----------------
__global__ void __launch_bounds__(256)
prop_kernel(const float* __restrict__ src, const float* __restrict__ h0,
            float* __restrict__ dst,
            const int* __restrict__ ptr, const int* __restrict__ rows,
            const float* __restrict__ norms, const float* __restrict__ dinv)
{
    int gw = (blockIdx.x * blockDim.x + threadIdx.x) >> 5;
    int lane = threadIdx.x & 31;
    if (gw >= NN) return;

    int beg = ptr[gw];
    int end = ptr[gw + 1];

    float acc = 0.0f;
    int i = beg;
    for (; i + 4 <= end; i += 4) {
        int   r0 = rows[i + 0], r1 = rows[i + 1], r2 = rows[i + 2], r3 = rows[i + 3];
        float w0 = norms[i + 0], w1 = norms[i + 1], w2 = norms[i + 2], w3 = norms[i + 3];
        float v0 = src[(size_t)r0 * OUTC + lane];
        float v1 = src[(size_t)r1 * OUTC + lane];
        float v2 = src[(size_t)r2 * OUTC + lane];
        float v3 = src[(size_t)r3 * OUTC + lane];
        acc = fmaf(w0, v0, acc);
        acc = fmaf(w1, v1, acc);
        acc = fmaf(w2, v2, acc);
        acc = fmaf(w3, v3, acc);
    }
    for (; i < end; ++i)
        acc = fmaf(norms[i], src[(size_t)rows[i] * OUTC + lane], acc);

    float dv = dinv[gw];
    acc = fmaf(dv * dv, src[(size_t)gw * OUTC + lane], acc);

    dst[(size_t)gw * OUTC + lane] =
        fmaf(1.0f - ALPHA, acc, ALPHA * h0[(size_t)gw * OUTC + lane]);
}

// ---------------- launch ----------------
extern "C" void kernel_launch(void* const* d_in, const int* in_sizes, int n_in,
                              void* d_out, int out_size)
{
    const float* x = nullptr; const int* ei = nullptr;
    const float *W1 = nullptr, *b1 = nullptr, *Wr = nullptr, *br = nullptr,
                *W2 = nullptr, *b2 = nullptr;
    for (int i = 0; i < n_in; i++) {
        switch (in_sizes[i]) {
            case 51200000: x  = (const float*)d_in[i]; break;
            case  3200000: ei = (const int*)d_in[i]; break;
            case   131072: W1 = (const float*)d_in[i]; break;
            case    65536: Wr = (const float*)d_in[i]; break;
            case     8192: W2 = (const float*)d_in[i]; break;
            case       32: b2 = (const float*)d_in[i]; break;
            case      256: if (!b1) b1 = (const float*)d_in[i];
                           else     br = (const float*)d_in[i]; break;
            default: break;
        }
    }
    if (!x || !ei || !W1 || !b1 || !Wr || !br || !W2 || !b2) {
        x  = (const float*)d_in[0];     ei = (const int*)d_in[1];
        W1 = (const float*)d_in[2];     b1 = (const float*)d_in[3];
        Wr = (const float*)d_in[4];     br = (const float*)d_in[5];
        W2 = (const float*)d_in[6];     b2 = (const float*)d_in[7];
    }
    float* out = (float*)d_out;

    float *h0, *hA, *hB, *dinv, *norms;
    int *deg, *ptr, *fil, *rows;
    __nv_bfloat16 *x2, *h12, *xr2, *w1s, *wrs, *w2s;
    cudaGetSymbolAddress((void**)&h0,    g_h0);
    cudaGetSymbolAddress((void**)&hA,    g_hA);
    cudaGetSymbolAddress((void**)&hB,    g_hB);
    cudaGetSymbolAddress((void**)&dinv,  g_dinv);
    cudaGetSymbolAddress((void**)&norms, g_norms);
    cudaGetSymbolAddress((void**)&deg,   g_deg);
    cudaGetSymbolAddress((void**)&ptr,   g_ptr);
    cudaGetSymbolAddress((void**)&fil,   g_fill);
    cudaGetSymbolAddress((void**)&rows,  g_rows);
    cudaGetSymbolAddress((void**)&x2,    g_x2);
    cudaGetSymbolAddress((void**)&h12,   g_h12);
    cudaGetSymbolAddress((void**)&xr2,   g_xr2);
    cudaGetSymbolAddress((void**)&w1s,   g_w1s);
    cudaGetSymbolAddress((void**)&wrs,   g_wrs);
    cudaGetSymbolAddress((void**)&w2s,   g_w2s);

    // dynamic smem: 2*A(18432) + 2*B
    const int smem_128 = 2 * 18432 + 2 * 128 * 144;  // 73728
    const int smem_32  = 2 * 18432 + 2 * 32 * 144;   // 46080
    cudaFuncSetAttribute(gemm_bf16<128, INC,  1>, cudaFuncAttributeMaxDynamicSharedMemorySize, smem_128);
    cudaFuncSetAttribute(gemm_bf16<128, HIDC, 2>, cudaFuncAttributeMaxDynamicSharedMemorySize, smem_128);
    cudaFuncSetAttribute(gemm_bf16<32,  HIDC, 0>, cudaFuncAttributeMaxDynamicSharedMemorySize, smem_32);

    // ---- fork: CSR build runs on side stream, concurrent with splits+GEMMs ----
    cudaEventRecord(g_evFork, 0);
    cudaStreamWaitEvent(g_sB, g_evFork, 0);
    init_kernel <<<(NN + 255) / 256, 256, 0, g_sB>>>(deg, fil);
    count_kernel<<<(EE + 255) / 256, 256, 0, g_sB>>>(ei, deg);
    dinv_kernel <<<(NN + 255) / 256, 256, 0, g_sB>>>(deg, dinv);
    scan_kernel <<<1, 1024, 0, g_sB>>>(deg, ptr);
    fill_kernel <<<(EE + 255) / 256, 256, 0, g_sB>>>(ei, ptr, fil, dinv, rows, norms);
    cudaEventRecord(g_evJoin, g_sB);

    // ---- splits (x + weights) on main stream ----
    split_act<<<(NN * (INC / 4) + 255) / 256, 256>>>(x, x2, NN, INC);
    split_act<<<(HIDC * (INC / 4) + 255) / 256, 256>>>(W1, w1s, HIDC, INC);
    split_act<<<(HIDC * (HIDC / 4) + 255) / 256, 256>>>(Wr, wrs, HIDC, HIDC);
    split_act<<<(OUTC * (HIDC / 4) + 255) / 256, 256>>>(W2, w2s, OUTC, HIDC);

    // ---- MLP (bf16 3-phase compensated tensor-core GEMMs, BN=128) ----
    const int ntiles = (NN + 127) / 128;
    gemm_bf16<128, INC,  1><<<dim3(ntiles, HIDC / 128), 256, smem_128>>>(
        x2,  w1s, b1, nullptr, h12, nullptr, NN, HIDC);
    gemm_bf16<128, HIDC, 2><<<dim3(ntiles, HIDC / 128), 256, smem_128>>>(
        h12, wrs, br, nullptr, xr2, h12,     NN, HIDC);
    gemm_bf16<32,  HIDC, 0><<<ntiles, 256, smem_32>>>(
        xr2, w2s, b2, h0,      nullptr, nullptr, NN, OUTC);

    // ---- join: CSR must be done before propagation ----
    cudaStreamWaitEvent(0, g_evJoin, 0);

    // ---- K = 10 propagation steps ----
    const int nblk = (NN * 32 + 255) / 256;
    prop_kernel<<<nblk, 256>>>(h0, h0, hA, ptr, rows, norms, dinv);
    prop_kernel<<<nblk, 256>>>(hA, h0, hB, ptr, rows, norms, dinv);
    prop_kernel<<<nblk, 256>>>(hB, h0, hA, ptr, rows, norms, dinv);
    prop_kernel<<<nblk, 256>>>(hA, h0, hB, ptr, rows, norms, dinv);
    prop_kernel<<<nblk, 256>>>(hB, h0, hA, ptr, rows, norms, dinv);
    prop_kernel<<<nblk, 256>>>(hA, h0, hB, ptr, rows, norms, dinv);
    prop_kernel<<<nblk, 256>>>(hB, h0, hA, ptr, rows, norms, dinv);
    prop_kernel<<<nblk, 256>>>(hA, h0, hB, ptr, rows, norms, dinv);
    prop_kernel<<<nblk, 256>>>(hB, h0, hA, ptr, rows, norms, dinv);
    prop_kernel<<<nblk, 256>>>(hA, h0, out, ptr, rows, norms, dinv);
}